// round 13
// baseline (speedup 1.0000x reference)
#include <cuda_runtime.h>
#include <cuda_fp16.h>
#include <math.h>

#define BATCH 8
#define CCH 96
#define HH 96
#define WW 96
#define HW (HH*WW)                 // 9216
#define NPIX 7077888               // 8*96*96*96
#define NPIX2 (NPIX/2)
#define N1OUT 14155776             // 8*192*96*96
#define NSPLIT 4

// weight layout: [chunk16ci][tap(9)][cotile(6)][lane(32)][4 frag words(half2)]
#define WCH2  6912
// patch smem: [ci2&3][row(10)][colpair]
#define PRS2  40
#define PCIS  400
#define PBUF  1600

// ---------------- scratch ----------------
__device__ float g_y1[NPIX];
__device__ float g_y2[NPIX];
__device__ float g_q [NPIX];       // lattice layout [b][p][c][l]
__device__ float g_k [NPIX];       // lattice layout
__device__ float g_y3[NPIX];
__device__ float g_attn4[NSPLIT*BATCH*CCH*CCH*9];
__device__ float g_mean[3*CCH];
__device__ float g_istd[3*CCH];

__device__ __align__(16) unsigned g_x1h[NPIX2];
__device__ __align__(16) unsigned g_x2h[NPIX2];
__device__ __align__(16) unsigned g_vh [NPIX2];
__device__ __align__(16) unsigned g_w1h [6*WCH2];
__device__ __align__(16) unsigned g_w2h [6*WCH2];
__device__ __align__(16) unsigned g_wa1h[12*WCH2];
__device__ __align__(16) unsigned g_wa2h[12*WCH2];
__device__ __align__(16) unsigned g_wa3h[12*WCH2];
__device__ __align__(16) unsigned g_wath[BATCH*6*WCH2];

struct ConvJob {
    const unsigned* inA;
    const unsigned* inB;
    const unsigned* wh;
    long  wstride;
    float* outf;
    unsigned* outh;
    int outmode;      // 0=NCHW fp32, 1=interleaved half2, 2=lattice fp32
    int csplit2;
    int cin2;
};
struct ConvJobs {
    ConvJob j[5];
};

__device__ __forceinline__ unsigned packh2(float a, float b) {
    __half2 h = __floats2half2_rn(a, b);
    return *(unsigned*)&h;
}

// ---------------- fp32 -> ci-pair-interleaved half2 ----------------
__global__ __launch_bounds__(256)
void cvt_pair_kernel(const float* __restrict__ s1, unsigned* __restrict__ d1,
                     const float* __restrict__ s2, unsigned* __restrict__ d2)
{
    const float* src = blockIdx.y ? s2 : s1;
    unsigned* dst    = blockIdx.y ? d2 : d1;
    int e = blockIdx.x*256 + threadIdx.x;
    if (e >= NPIX2) return;
    int b = e / (48*HW), r = e - b*48*HW;
    int ci2 = r / HW, hw = r - ci2*HW;
    size_t off = ((size_t)b*CCH + 2*ci2)*HW + hw;
    dst[e] = packh2(src[off], src[off + HW]);
}

// ---------------- weight pre-transform ----------------
__global__ __launch_bounds__(256)
void wprep_all_kernel(const float* __restrict__ w1, const float* __restrict__ w2,
                      const float* __restrict__ wa1, const float* __restrict__ wa2,
                      const float* __restrict__ wa3,
                      unsigned* __restrict__ d1, unsigned* __restrict__ d2,
                      unsigned* __restrict__ d3, unsigned* __restrict__ d4,
                      unsigned* __restrict__ d5)
{
    const int id = blockIdx.y;
    const float* src; unsigned* dst; int cin;
    if      (id == 0) { src = w1;  dst = d1; cin = 96;  }
    else if (id == 1) { src = w2;  dst = d2; cin = 96;  }
    else if (id == 2) { src = wa1; dst = d3; cin = 192; }
    else if (id == 3) { src = wa2; dst = d4; cin = 192; }
    else              { src = wa3; dst = d5; cin = 192; }
    const int nwords = (cin >> 4) * WCH2;
    int e = blockIdx.x*256 + threadIdx.x;
    if (e >= nwords) return;
    int chunk = e / WCH2, rm = e - chunk*WCH2;
    int w = rm & 3, lane = (rm >> 2) & 31, mtap = rm >> 7;
    int tap = mtap / 6, mt = mtap - 6*tap;
    int g = lane >> 2, t = lane & 3;
    int co = mt*16 + g + (w & 1)*8;
    int ci = chunk*16 + 2*t + ((w >> 1) & 1)*8;
    dst[e] = packh2(src[((size_t)co*cin + ci)*9 + tap],
                    src[((size_t)co*cin + ci + 1)*9 + tap]);
}

// ---------------- tensor-core 3x3 conv, fp16 m16n8k16, multi-job -----------
__global__ __launch_bounds__(192, 2)
void conv3x3_fp16_kernel(ConvJobs jobs)
{
    extern __shared__ unsigned dsm[];
    const ConvJob J = jobs.j[blockIdx.y];
    const unsigned* __restrict__ inAh = J.inA;
    const unsigned* __restrict__ inBh = J.inB;
    const int csplit2 = J.csplit2, cin2 = J.cin2;

    const int tid  = threadIdx.x;
    const int lane = tid & 31, wid = tid >> 5;
    const int g = lane >> 2, t = lane & 3;
    const int cog = wid >> 1;
    const int rp  = wid & 1;
    const int b   = blockIdx.z;
    const int byk = blockIdx.x / 6, bxk = blockIdx.x - 6*byk;
    const int by0 = byk*8, bx0 = bxk*16;

    const unsigned smem_b = (unsigned)__cvta_generic_to_shared(dsm);
    unsigned* psmem = dsm + 2*WCH2;

    int pgoff[8], psoff[8], pci[8];
    bool lok[8], sok[8];
    #pragma unroll
    for (int it = 0; it < 8; it++) {
        int e = tid + it*192;
        int ci = e / 180, r2 = e - ci*180;
        int row = r2 / 18, col = r2 - row*18;
        int gh = by0 + row - 1, gw = bx0 + col - 1;
        bool inp = (e < 1440);
        bool ok = inp && gh >= 0 && gh < HH && gw >= 0 && gw < WW;
        lok[it] = ok; sok[it] = inp;
        pgoff[it] = ok ? gh*WW + gw : 0;
        psoff[it] = inp ? (ci & 3)*PCIS + row*PRS2 + col*2 + (ci >> 2) : 0;
        pci[it]   = ci;
    }

    const unsigned* wsrc0 = J.wh + (size_t)J.wstride*b;

    #pragma unroll
    for (int k2 = 0; k2 < 9; k2++) {
        int idx = tid + k2*192;
        asm volatile("cp.async.cg.shared.global [%0], [%1], 16;"
                     :: "r"(smem_b + idx*16), "l"(wsrc0 + idx*4) : "memory");
    }
    asm volatile("cp.async.commit_group;" ::: "memory");
    {
        unsigned pv[8];
        #pragma unroll
        for (int it = 0; it < 8; it++) {
            int gci = pci[it];
            const unsigned* src = (gci < csplit2)
                ? inAh + ((size_t)b*csplit2 + gci)*HW
                : inBh + ((size_t)b*(cin2-csplit2) + (gci-csplit2))*HW;
            pv[it] = lok[it] ? src[pgoff[it]] : 0u;
        }
        #pragma unroll
        for (int it = 0; it < 8; it++)
            if (sok[it]) psmem[psoff[it]] = pv[it];
    }
    asm volatile("cp.async.wait_group 0;" ::: "memory");
    __syncthreads();

    float acc[2][8][4];
    #pragma unroll
    for (int m=0;m<2;m++)
        #pragma unroll
        for (int nt=0;nt<8;nt++)
            #pragma unroll
            for (int r=0;r<4;r++) acc[m][nt][r] = 0.f;

    const int nchunk = cin2 >> 3;
    for (int ch = 0; ch < nchunk; ch++) {
        const int cur = ch & 1;
        const bool more = (ch + 1 < nchunk);

        unsigned pv[8];
        if (more) {
            const unsigned* wsrc = wsrc0 + (size_t)(ch+1)*WCH2;
            const unsigned wdst = smem_b + (cur^1)*WCH2*4;
            #pragma unroll
            for (int k2 = 0; k2 < 9; k2++) {
                int idx = tid + k2*192;
                asm volatile("cp.async.cg.shared.global [%0], [%1], 16;"
                             :: "r"(wdst + idx*16), "l"(wsrc + idx*4) : "memory");
            }
            asm volatile("cp.async.commit_group;" ::: "memory");
            const int ci0 = (ch+1) << 3;
            #pragma unroll
            for (int it = 0; it < 8; it++) {
                int gci = ci0 + pci[it];
                const unsigned* src = (gci < csplit2)
                    ? inAh + ((size_t)b*csplit2 + gci)*HW
                    : inBh + ((size_t)b*(cin2-csplit2) + (gci-csplit2))*HW;
                pv[it] = lok[it] ? src[pgoff[it]] : 0u;
            }
        }

        const unsigned wbase = smem_b + cur*WCH2*4;
        const unsigned pbase = smem_b + (2*WCH2 + cur*PBUF)*4;
        #pragma unroll
        for (int tap = 0; tap < 9; tap++) {
            const int i = tap/3, j = tap - 3*(tap/3);
            unsigned a[2][4];
            #pragma unroll
            for (int m = 0; m < 2; m++) {
                const int mt = cog*2 + m;
                asm volatile("ld.shared.v4.b32 {%0,%1,%2,%3}, [%4];"
                    : "=r"(a[m][0]), "=r"(a[m][1]), "=r"(a[m][2]), "=r"(a[m][3])
                    : "r"(wbase + (((tap*6 + mt)*32 + lane)*16)));
            }
            #pragma unroll
            for (int nt = 0; nt < 8; nt++) {
                const int py = 4*rp + (nt & 3);
                const int cb2 = (nt >> 2) * 8;
                unsigned b0, b1;
                asm volatile("ld.shared.v2.b32 {%0,%1}, [%2];"
                    : "=r"(b0), "=r"(b1)
                    : "r"(pbase + (t*PCIS + (py+i)*PRS2 + (cb2+j+g)*2)*4));
                #pragma unroll
                for (int m = 0; m < 2; m++) {
                    asm volatile(
                        "mma.sync.aligned.m16n8k16.row.col.f32.f16.f16.f32 "
                        "{%0,%1,%2,%3}, {%4,%5,%6,%7}, {%8,%9}, {%0,%1,%2,%3};"
                        : "+f"(acc[m][nt][0]), "+f"(acc[m][nt][1]),
                          "+f"(acc[m][nt][2]), "+f"(acc[m][nt][3])
                        : "r"(a[m][0]), "r"(a[m][1]), "r"(a[m][2]), "r"(a[m][3]),
                          "r"(b0), "r"(b1));
                }
            }
        }

        if (more) {
            unsigned* pd = psmem + (cur^1)*PBUF;
            #pragma unroll
            for (int it = 0; it < 8; it++)
                if (sok[it]) pd[psoff[it]] = pv[it];
            asm volatile("cp.async.wait_group 0;" ::: "memory");
        }
        __syncthreads();
    }

    // ---- writeback ----
    if (J.outmode == 0) {
        float* out = J.outf;
        #pragma unroll
        for (int m = 0; m < 2; m++)
            #pragma unroll
            for (int nt = 0; nt < 8; nt++) {
                int co  = cog*32 + m*16 + g;
                int row = by0 + 4*rp + (nt & 3);
                int col = bx0 + (nt >> 2)*8 + 2*t;
                size_t base = (((size_t)b*CCH + co)*HH + row)*WW + col;
                *(float2*)&out[base]        = make_float2(acc[m][nt][0], acc[m][nt][1]);
                *(float2*)&out[base + 8*HW] = make_float2(acc[m][nt][2], acc[m][nt][3]);
            }
    } else if (J.outmode == 2) {
        // lattice layout: out[((b*9+p)*96+co)*1024 + l], p=(row%3)*3+col%3
        float* out = J.outf;
        #pragma unroll
        for (int m = 0; m < 2; m++)
            #pragma unroll
            for (int nt = 0; nt < 8; nt++) {
                int co  = cog*32 + m*16 + g;
                int row = by0 + 4*rp + (nt & 3);
                int col = bx0 + (nt >> 2)*8 + 2*t;
                int i = row % 3, hh = row / 3;
                #pragma unroll
                for (int d = 0; d < 2; d++) {
                    int cc = col + d;
                    int j = cc % 3, ww = cc / 3;
                    int p = i*3 + j, l = hh*32 + ww;
                    size_t base = (((size_t)b*9 + p)*CCH)*1024 + l;
                    out[base + (size_t)co*1024]       = acc[m][nt][d];
                    out[base + (size_t)(co + 8)*1024] = acc[m][nt][2 + d];
                }
            }
    } else {
        unsigned* outh = J.outh;
        #pragma unroll
        for (int m = 0; m < 2; m++)
            #pragma unroll
            for (int nt = 0; nt < 8; nt++) {
                float a0 = acc[m][nt][0], a1 = acc[m][nt][1];
                float a2 = acc[m][nt][2], a3 = acc[m][nt][3];
                float p0 = __shfl_xor_sync(0xFFFFFFFFu, a0, 4);
                float p1 = __shfl_xor_sync(0xFFFFFFFFu, a1, 4);
                float p2 = __shfl_xor_sync(0xFFFFFFFFu, a2, 4);
                float p3 = __shfl_xor_sync(0xFFFFFFFFu, a3, 4);
                int row = by0 + 4*rp + (nt & 3);
                int col = bx0 + (nt >> 2)*8 + 2*t;
                int B = cog*32 + m*16;
                int ci2; unsigned w0, w1;
                if ((g & 1) == 0) {
                    ci2 = (B >> 1) + (g >> 1);
                    w0 = packh2(a0, p0); w1 = packh2(a1, p1);
                } else {
                    ci2 = (B >> 1) + 4 + ((g - 1) >> 1);
                    w0 = packh2(p2, a2); w1 = packh2(p3, a3);
                }
                *(uint2*)&outh[((size_t)b*48 + ci2)*HW + row*WW + col] =
                    make_uint2(w0, w1);
            }
    }
}

// ---------------- attention GEMM, split-K x4, lattice layout ----------------
// grid (9, 8, 4). q/k in [b][p][c][l] -> fully coalesced loads.
__global__ __launch_bounds__(256)
void attn_split_kernel(const float* __restrict__ qlat, const float* __restrict__ klat,
                       float* __restrict__ attn4)
{
    const int p = blockIdx.x;
    const int b = blockIdx.y;
    const int ks = blockIdx.z;
    const int tid = threadIdx.y*16 + threadIdx.x;

    __shared__ float Qs[16][102];
    __shared__ float Ks[16][102];

    const float* qb = qlat + ((size_t)(b*9 + p)*CCH)*1024;
    const float* kb = klat + ((size_t)(b*9 + p)*CCH)*1024;

    float acc[6][6];
    #pragma unroll
    for (int r=0;r<6;r++)
        #pragma unroll
        for (int s=0;s<6;s++) acc[r][s]=0.f;

    const int kk = tid & 15;
    const int cb = tid >> 4;
    const int lbase = ks*256;
    for (int l0 = lbase; l0 < lbase + 256; l0 += 16) {
        #pragma unroll
        for (int it = 0; it < 6; it++) {
            int c = cb + it*16;
            Qs[kk][c] = qb[(size_t)c*1024 + l0 + kk];
            Ks[kk][c] = kb[(size_t)c*1024 + l0 + kk];
        }
        __syncthreads();
        #pragma unroll
        for (int k2=0; k2<16; k2++) {
            float rq[6], rk[6];
            #pragma unroll
            for (int r=0;r<6;r++) {
                rq[r] = Qs[k2][threadIdx.y*6 + r];
                rk[r] = Ks[k2][threadIdx.x*6 + r];
            }
            #pragma unroll
            for (int r=0;r<6;r++)
                #pragma unroll
                for (int s=0;s<6;s++)
                    acc[r][s] = fmaf(rq[r], rk[s], acc[r][s]);
        }
        __syncthreads();
    }
    #pragma unroll
    for (int r=0;r<6;r++)
        #pragma unroll
        for (int s=0;s<6;s++) {
            int cq = threadIdx.y*6 + r, ck = threadIdx.x*6 + s;
            attn4[((size_t)(ks*768 + b*CCH + ck))*864 + cq*9 + p] = acc[r][s];
        }
}

// ---------------- softmax + direct fragment-layout weight emit -------------
__global__ __launch_bounds__(256)
void softmax_kernel(const float* __restrict__ attn4, unsigned* __restrict__ wath)
{
    const int rowid = blockIdx.x;          // b*96 + ck
    const float scale = 0.034020690871988585f;   // 1/sqrt(864)
    const int tid = threadIdx.x;
    __shared__ float red[256];
    __shared__ float sm[864];

    float v[4];
    float mx = -1e30f;
    #pragma unroll
    for (int it=0; it<4; it++) {
        int idx = tid + it*256;
        float s = -1e30f;
        if (idx < 864) {
            s = 0.f;
            #pragma unroll
            for (int ks = 0; ks < NSPLIT; ks++)
                s += attn4[((size_t)(ks*768 + rowid))*864 + idx];
            s *= scale;
        }
        v[it] = s;
        mx = fmaxf(mx, s);
    }
    red[tid] = mx; __syncthreads();
    for (int s=128; s>0; s>>=1) { if (tid<s) red[tid]=fmaxf(red[tid],red[tid+s]); __syncthreads(); }
    mx = red[0]; __syncthreads();

    float sum = 0.f;
    #pragma unroll
    for (int it=0; it<4; it++) {
        int idx = tid + it*256;
        v[it] = (idx < 864) ? expf(v[it]-mx) : 0.f;
        sum += v[it];
    }
    red[tid] = sum; __syncthreads();
    for (int s=128; s>0; s>>=1) { if (tid<s) red[tid]+=red[tid+s]; __syncthreads(); }
    float inv = 1.f/red[0];
    __syncthreads();

    #pragma unroll
    for (int it=0; it<4; it++) {
        int idx = tid + it*256;
        if (idx < 864) sm[idx] = v[it]*inv;
    }
    __syncthreads();

    const int bb = rowid / CCH, ck = rowid - (rowid/CCH)*CCH;
    const int mt = ck >> 4, gq = ck & 7, hiw = (ck >> 3) & 1;
    #pragma unroll
    for (int it = 0; it < 2; it++) {
        int e = tid + it*256;
        if (e < 432) {
            int u = e / 9, tap = e - 9*u;
            int chunk = u >> 3, hi2 = (u & 7) >> 2, t = u & 3;
            int w = hiw | (hi2 << 1);
            int lane = (gq << 2) | t;
            wath[(size_t)bb*6*WCH2 + chunk*WCH2 + ((tap*6 + mt)*32 + lane)*4 + w] =
                packh2(sm[2*u*9 + tap], sm[(2*u + 1)*9 + tap]);
        }
    }
}

// ---------------- batchnorm statistics (biased var) ----------------
__global__ __launch_bounds__(256)
void bnstats_kernel(const float* __restrict__ y1, const float* __restrict__ y2,
                    const float* __restrict__ y3,
                    float* __restrict__ meanv, float* __restrict__ istdv)
{
    const int t = blockIdx.x / CCH, c = blockIdx.x - t*CCH;
    const float* src = (t==0) ? y1 : (t==1) ? y2 : y3;
    float s = 0.f, sq = 0.f;
    for (int e = threadIdx.x; e < BATCH*HW; e += 256) {
        int b = e / HW, hw = e - b*HW;
        float vv = src[((size_t)b*CCH + c)*HW + hw];
        s += vv; sq = fmaf(vv, vv, sq);
    }
    __shared__ float sh1[256], sh2[256];
    sh1[threadIdx.x]=s; sh2[threadIdx.x]=sq;
    __syncthreads();
    for (int st=128; st>0; st>>=1) {
        if (threadIdx.x < st) { sh1[threadIdx.x]+=sh1[threadIdx.x+st]; sh2[threadIdx.x]+=sh2[threadIdx.x+st]; }
        __syncthreads();
    }
    if (threadIdx.x==0) {
        const float invN = 1.f / (float)(BATCH*HW);
        float m = sh1[0]*invN;
        float var = sh2[0]*invN - m*m;
        meanv[blockIdx.x] = m;
        istdv[blockIdx.x] = rsqrtf(var + 1e-5f);
    }
}

// ---------------- final fuse: out = (x+y, x) ----------------
__global__ __launch_bounds__(256)
void finalize_kernel(const float* __restrict__ x1, const float* __restrict__ x2,
                     const float* __restrict__ y1, const float* __restrict__ y2,
                     const float* __restrict__ y3,
                     const float* __restrict__ meanv, const float* __restrict__ istdv,
                     float* __restrict__ out, int writeSecond)
{
    int idx = blockIdx.x*256 + threadIdx.x;
    if (idx >= N1OUT) return;
    int hw = idx % HW;
    int c  = (idx / HW) % (2*CCH);
    int b  = idx / (HW*2*CCH);
    float xv, yv;
    if (c < CCH) {
        size_t off = ((size_t)b*CCH + c)*HW + hw;
        xv = x1[off];
        float a = (y1[off]-meanv[c])       * istdv[c];
        float g = (y2[off]-meanv[CCH+c])   * istdv[CCH+c];
        yv = a*g;
    } else {
        int cc = c - CCH;
        size_t off = ((size_t)b*CCH + cc)*HW + hw;
        xv = x2[off];
        yv = (y3[off]-meanv[2*CCH+cc]) * istdv[2*CCH+cc];
    }
    out[idx] = xv + yv;
    if (writeSecond) out[N1OUT + idx] = xv;
}

// ---------------- launch ----------------
extern "C" void kernel_launch(void* const* d_in, const int* in_sizes, int n_in,
                              void* d_out, int out_size)
{
    const float* x1  = (const float*)d_in[0];
    const float* x2  = (const float*)d_in[1];
    const float* w1  = (const float*)d_in[2];
    const float* w2  = (const float*)d_in[3];
    const float* wa1 = (const float*)d_in[4];
    const float* wa2 = (const float*)d_in[5];
    const float* wa3 = (const float*)d_in[6];
    float* out = (float*)d_out;

    float *y1,*y2,*q,*k,*y3,*attn4,*meanv,*istdv;
    unsigned *x1h,*x2h,*vh,*w1h,*w2h,*wa1h,*wa2h,*wa3h,*wath;
    cudaGetSymbolAddress((void**)&y1,   g_y1);
    cudaGetSymbolAddress((void**)&y2,   g_y2);
    cudaGetSymbolAddress((void**)&q,    g_q);
    cudaGetSymbolAddress((void**)&k,    g_k);
    cudaGetSymbolAddress((void**)&y3,   g_y3);
    cudaGetSymbolAddress((void**)&attn4,g_attn4);
    cudaGetSymbolAddress((void**)&meanv,g_mean);
    cudaGetSymbolAddress((void**)&istdv,g_istd);
    cudaGetSymbolAddress((void**)&x1h,  g_x1h);
    cudaGetSymbolAddress((void**)&x2h,  g_x2h);
    cudaGetSymbolAddress((void**)&vh,   g_vh);
    cudaGetSymbolAddress((void**)&w1h,  g_w1h);
    cudaGetSymbolAddress((void**)&w2h,  g_w2h);
    cudaGetSymbolAddress((void**)&wa1h, g_wa1h);
    cudaGetSymbolAddress((void**)&wa2h, g_wa2h);
    cudaGetSymbolAddress((void**)&wa3h, g_wa3h);
    cudaGetSymbolAddress((void**)&wath, g_wath);

    static int smem_set = 0;
    const int CONV_SMEM = (2*WCH2 + 2*PBUF) * 4;   // 68096 B
    if (!smem_set) {
        cudaFuncSetAttribute(conv3x3_fp16_kernel,
                             cudaFuncAttributeMaxDynamicSharedMemorySize, CONV_SMEM);
        smem_set = 1;
    }

    // 1. inputs -> interleaved half2
    cvt_pair_kernel<<<dim3((NPIX2+255)/256, 2), 256>>>(x1, x1h, x2, x2h);

    // 2. all fixed weights -> fp16 fragment layout
    wprep_all_kernel<<<dim3((12*WCH2+255)/256, 5), 256>>>(
        w1, w2, wa1, wa2, wa3, w1h, w2h, wa1h, wa2h, wa3h);

    // 3. ALL five independent convs in one launch (q,k in lattice layout)
    {
        ConvJobs jb{};
        jb.j[0] = { x1h, x1h, w1h,  0, y1, 0, 0, 48, 48 };
        jb.j[1] = { x2h, x2h, w2h,  0, y2, 0, 0, 48, 48 };
        jb.j[2] = { x1h, x2h, wa1h, 0, q,  0, 2, 48, 96 };
        jb.j[3] = { x1h, x2h, wa2h, 0, k,  0, 2, 48, 96 };
        jb.j[4] = { x1h, x2h, wa3h, 0, 0, vh, 1, 48, 96 };
        conv3x3_fp16_kernel<<<dim3(72, 5, 8), 192, CONV_SMEM>>>(jb);
    }

    // 4. attention logits (split-K x4, coalesced) + softmax -> conv weights
    attn_split_kernel<<<dim3(9, 8, NSPLIT), dim3(16,16)>>>(q, k, attn4);
    softmax_kernel<<<BATCH*CCH, 256>>>(attn4, wath);

    // 5. attn @ v_unf == per-batch 3x3 conv
    {
        ConvJobs jb{};
        jb.j[0] = { vh, vh, wath, 6L*WCH2, y3, 0, 0, 48, 48 };
        conv3x3_fp16_kernel<<<dim3(72, 1, 8), 192, CONV_SMEM>>>(jb);
    }

    // 6. batchnorm stats + fused epilogue
    bnstats_kernel<<<3*CCH, 256>>>(y1, y2, y3, meanv, istdv);
    int writeSecond = (out_size >= 2*N1OUT) ? 1 : 0;
    finalize_kernel<<<(N1OUT + 255)/256, 256>>>(x1, x2, y1, y2, y3, meanv, istdv, out, writeSecond);
}

// round 14
// speedup vs baseline: 1.0871x; 1.0871x over previous
#include <cuda_runtime.h>
#include <cuda_fp16.h>
#include <math.h>

#define BATCH 8
#define CCH 96
#define HH 96
#define WW 96
#define HW (HH*WW)                 // 9216
#define NPIX 7077888               // 8*96*96*96
#define NPIX2 (NPIX/2)
#define N1OUT 14155776             // 8*192*96*96
#define NSPLIT 4

// weight layout: [chunk16ci][tap(9)][cotile(6)][lane(32)][4 frag words(half2)]
#define WCH2  6912
// patch smem: [ci2&3][row(10)][colpair]
#define PRS2  40
#define PCIS  400
#define PBUF  1600

// ---------------- scratch ----------------
__device__ float g_y1[NPIX];
__device__ float g_y2[NPIX];
__device__ float g_y3[NPIX];
__device__ float g_attn4[NSPLIT*BATCH*CCH*CCH*9];
__device__ float g_mean[3*CCH];
__device__ float g_istd[3*CCH];

// interleaved half2 buffers
__device__ __align__(16) unsigned g_x1h[NPIX2];
__device__ __align__(16) unsigned g_x2h[NPIX2];
__device__ __align__(16) unsigned g_qh [NPIX2];
__device__ __align__(16) unsigned g_kh [NPIX2];
__device__ __align__(16) unsigned g_vh [NPIX2];
// fragment-order fp16 weights
__device__ __align__(16) unsigned g_w1h [6*WCH2];
__device__ __align__(16) unsigned g_w2h [6*WCH2];
__device__ __align__(16) unsigned g_wa1h[12*WCH2];
__device__ __align__(16) unsigned g_wa2h[12*WCH2];
__device__ __align__(16) unsigned g_wa3h[12*WCH2];
__device__ __align__(16) unsigned g_wath[BATCH*6*WCH2];

struct ConvJob {
    const unsigned* inA;
    const unsigned* inB;
    const unsigned* wh;
    long  wstride;
    float* outf;
    unsigned* outh;
    int outmode;      // 0=NCHW fp32, 1=interleaved half2
    int csplit2;
    int cin2;
};
struct ConvJobs {
    ConvJob j[5];
};

__device__ __forceinline__ unsigned packh2(float a, float b) {
    __half2 h = __floats2half2_rn(a, b);
    return *(unsigned*)&h;
}

// ---------------- fp32 -> ci-pair-interleaved half2 ----------------
__global__ __launch_bounds__(256)
void cvt_pair_kernel(const float* __restrict__ s1, unsigned* __restrict__ d1,
                     const float* __restrict__ s2, unsigned* __restrict__ d2)
{
    const float* src = blockIdx.y ? s2 : s1;
    unsigned* dst    = blockIdx.y ? d2 : d1;
    int e = blockIdx.x*256 + threadIdx.x;
    if (e >= NPIX2) return;
    int b = e / (48*HW), r = e - b*48*HW;
    int ci2 = r / HW, hw = r - ci2*HW;
    size_t off = ((size_t)b*CCH + 2*ci2)*HW + hw;
    dst[e] = packh2(src[off], src[off + HW]);
}

// ---------------- weight pre-transform ----------------
__global__ __launch_bounds__(256)
void wprep_all_kernel(const float* __restrict__ w1, const float* __restrict__ w2,
                      const float* __restrict__ wa1, const float* __restrict__ wa2,
                      const float* __restrict__ wa3,
                      unsigned* __restrict__ d1, unsigned* __restrict__ d2,
                      unsigned* __restrict__ d3, unsigned* __restrict__ d4,
                      unsigned* __restrict__ d5)
{
    const int id = blockIdx.y;
    const float* src; unsigned* dst; int cin;
    if      (id == 0) { src = w1;  dst = d1; cin = 96;  }
    else if (id == 1) { src = w2;  dst = d2; cin = 96;  }
    else if (id == 2) { src = wa1; dst = d3; cin = 192; }
    else if (id == 3) { src = wa2; dst = d4; cin = 192; }
    else              { src = wa3; dst = d5; cin = 192; }
    const int nwords = (cin >> 4) * WCH2;
    int e = blockIdx.x*256 + threadIdx.x;
    if (e >= nwords) return;
    int chunk = e / WCH2, rm = e - chunk*WCH2;
    int w = rm & 3, lane = (rm >> 2) & 31, mtap = rm >> 7;
    int tap = mtap / 6, mt = mtap - 6*tap;
    int g = lane >> 2, t = lane & 3;
    int co = mt*16 + g + (w & 1)*8;
    int ci = chunk*16 + 2*t + ((w >> 1) & 1)*8;
    dst[e] = packh2(src[((size_t)co*cin + ci)*9 + tap],
                    src[((size_t)co*cin + ci + 1)*9 + tap]);
}

// ---------------- tensor-core 3x3 conv, fp16 m16n8k16, multi-job -----------
__global__ __launch_bounds__(192, 2)
void conv3x3_fp16_kernel(ConvJobs jobs)
{
    extern __shared__ unsigned dsm[];
    const ConvJob J = jobs.j[blockIdx.y];
    const unsigned* __restrict__ inAh = J.inA;
    const unsigned* __restrict__ inBh = J.inB;
    const int csplit2 = J.csplit2, cin2 = J.cin2;

    const int tid  = threadIdx.x;
    const int lane = tid & 31, wid = tid >> 5;
    const int g = lane >> 2, t = lane & 3;
    const int cog = wid >> 1;
    const int rp  = wid & 1;
    const int b   = blockIdx.z;
    const int byk = blockIdx.x / 6, bxk = blockIdx.x - 6*byk;
    const int by0 = byk*8, bx0 = bxk*16;

    const unsigned smem_b = (unsigned)__cvta_generic_to_shared(dsm);
    unsigned* psmem = dsm + 2*WCH2;

    int pgoff[8], psoff[8], pci[8];
    bool lok[8], sok[8];
    #pragma unroll
    for (int it = 0; it < 8; it++) {
        int e = tid + it*192;
        int ci = e / 180, r2 = e - ci*180;
        int row = r2 / 18, col = r2 - row*18;
        int gh = by0 + row - 1, gw = bx0 + col - 1;
        bool inp = (e < 1440);
        bool ok = inp && gh >= 0 && gh < HH && gw >= 0 && gw < WW;
        lok[it] = ok; sok[it] = inp;
        pgoff[it] = ok ? gh*WW + gw : 0;
        psoff[it] = inp ? (ci & 3)*PCIS + row*PRS2 + col*2 + (ci >> 2) : 0;
        pci[it]   = ci;
    }

    const unsigned* wsrc0 = J.wh + (size_t)J.wstride*b;

    #pragma unroll
    for (int k2 = 0; k2 < 9; k2++) {
        int idx = tid + k2*192;
        asm volatile("cp.async.cg.shared.global [%0], [%1], 16;"
                     :: "r"(smem_b + idx*16), "l"(wsrc0 + idx*4) : "memory");
    }
    asm volatile("cp.async.commit_group;" ::: "memory");
    {
        unsigned pv[8];
        #pragma unroll
        for (int it = 0; it < 8; it++) {
            int gci = pci[it];
            const unsigned* src = (gci < csplit2)
                ? inAh + ((size_t)b*csplit2 + gci)*HW
                : inBh + ((size_t)b*(cin2-csplit2) + (gci-csplit2))*HW;
            pv[it] = lok[it] ? src[pgoff[it]] : 0u;
        }
        #pragma unroll
        for (int it = 0; it < 8; it++)
            if (sok[it]) psmem[psoff[it]] = pv[it];
    }
    asm volatile("cp.async.wait_group 0;" ::: "memory");
    __syncthreads();

    float acc[2][8][4];
    #pragma unroll
    for (int m=0;m<2;m++)
        #pragma unroll
        for (int nt=0;nt<8;nt++)
            #pragma unroll
            for (int r=0;r<4;r++) acc[m][nt][r] = 0.f;

    const int nchunk = cin2 >> 3;
    for (int ch = 0; ch < nchunk; ch++) {
        const int cur = ch & 1;
        const bool more = (ch + 1 < nchunk);

        unsigned pv[8];
        if (more) {
            const unsigned* wsrc = wsrc0 + (size_t)(ch+1)*WCH2;
            const unsigned wdst = smem_b + (cur^1)*WCH2*4;
            #pragma unroll
            for (int k2 = 0; k2 < 9; k2++) {
                int idx = tid + k2*192;
                asm volatile("cp.async.cg.shared.global [%0], [%1], 16;"
                             :: "r"(wdst + idx*16), "l"(wsrc + idx*4) : "memory");
            }
            asm volatile("cp.async.commit_group;" ::: "memory");
            const int ci0 = (ch+1) << 3;
            #pragma unroll
            for (int it = 0; it < 8; it++) {
                int gci = ci0 + pci[it];
                const unsigned* src = (gci < csplit2)
                    ? inAh + ((size_t)b*csplit2 + gci)*HW
                    : inBh + ((size_t)b*(cin2-csplit2) + (gci-csplit2))*HW;
                pv[it] = lok[it] ? src[pgoff[it]] : 0u;
            }
        }

        const unsigned wbase = smem_b + cur*WCH2*4;
        const unsigned pbase = smem_b + (2*WCH2 + cur*PBUF)*4;
        #pragma unroll
        for (int tap = 0; tap < 9; tap++) {
            const int i = tap/3, j = tap - 3*(tap/3);
            unsigned a[2][4];
            #pragma unroll
            for (int m = 0; m < 2; m++) {
                const int mt = cog*2 + m;
                asm volatile("ld.shared.v4.b32 {%0,%1,%2,%3}, [%4];"
                    : "=r"(a[m][0]), "=r"(a[m][1]), "=r"(a[m][2]), "=r"(a[m][3])
                    : "r"(wbase + (((tap*6 + mt)*32 + lane)*16)));
            }
            #pragma unroll
            for (int nt = 0; nt < 8; nt++) {
                const int py = 4*rp + (nt & 3);
                const int cb2 = (nt >> 2) * 8;
                unsigned b0, b1;
                asm volatile("ld.shared.v2.b32 {%0,%1}, [%2];"
                    : "=r"(b0), "=r"(b1)
                    : "r"(pbase + (t*PCIS + (py+i)*PRS2 + (cb2+j+g)*2)*4));
                #pragma unroll
                for (int m = 0; m < 2; m++) {
                    asm volatile(
                        "mma.sync.aligned.m16n8k16.row.col.f32.f16.f16.f32 "
                        "{%0,%1,%2,%3}, {%4,%5,%6,%7}, {%8,%9}, {%0,%1,%2,%3};"
                        : "+f"(acc[m][nt][0]), "+f"(acc[m][nt][1]),
                          "+f"(acc[m][nt][2]), "+f"(acc[m][nt][3])
                        : "r"(a[m][0]), "r"(a[m][1]), "r"(a[m][2]), "r"(a[m][3]),
                          "r"(b0), "r"(b1));
                }
            }
        }

        if (more) {
            unsigned* pd = psmem + (cur^1)*PBUF;
            #pragma unroll
            for (int it = 0; it < 8; it++)
                if (sok[it]) pd[psoff[it]] = pv[it];
            asm volatile("cp.async.wait_group 0;" ::: "memory");
        }
        __syncthreads();
    }

    // ---- writeback ----
    if (J.outmode == 0) {
        float* out = J.outf;
        #pragma unroll
        for (int m = 0; m < 2; m++)
            #pragma unroll
            for (int nt = 0; nt < 8; nt++) {
                int co  = cog*32 + m*16 + g;
                int row = by0 + 4*rp + (nt & 3);
                int col = bx0 + (nt >> 2)*8 + 2*t;
                size_t base = (((size_t)b*CCH + co)*HH + row)*WW + col;
                *(float2*)&out[base]        = make_float2(acc[m][nt][0], acc[m][nt][1]);
                *(float2*)&out[base + 8*HW] = make_float2(acc[m][nt][2], acc[m][nt][3]);
            }
    } else {
        unsigned* outh = J.outh;
        #pragma unroll
        for (int m = 0; m < 2; m++)
            #pragma unroll
            for (int nt = 0; nt < 8; nt++) {
                float a0 = acc[m][nt][0], a1 = acc[m][nt][1];
                float a2 = acc[m][nt][2], a3 = acc[m][nt][3];
                float p0 = __shfl_xor_sync(0xFFFFFFFFu, a0, 4);
                float p1 = __shfl_xor_sync(0xFFFFFFFFu, a1, 4);
                float p2 = __shfl_xor_sync(0xFFFFFFFFu, a2, 4);
                float p3 = __shfl_xor_sync(0xFFFFFFFFu, a3, 4);
                int row = by0 + 4*rp + (nt & 3);
                int col = bx0 + (nt >> 2)*8 + 2*t;
                int B = cog*32 + m*16;
                int ci2; unsigned w0, w1;
                if ((g & 1) == 0) {
                    ci2 = (B >> 1) + (g >> 1);
                    w0 = packh2(a0, p0); w1 = packh2(a1, p1);
                } else {
                    ci2 = (B >> 1) + 4 + ((g - 1) >> 1);
                    w0 = packh2(p2, a2); w1 = packh2(p3, a3);
                }
                *(uint2*)&outh[((size_t)b*48 + ci2)*HW + row*WW + col] =
                    make_uint2(w0, w1);
            }
    }
}

// ---------------- attention GEMM, split-K x4, half2 q/k ----------------
// grid (9, 8, 4). q/k interleaved half2: word[(b*48+ci2)*HW + hw] = {2ci2, 2ci2+1}
__global__ __launch_bounds__(256)
void attn_split_kernel(const unsigned* __restrict__ qh, const unsigned* __restrict__ kh,
                       float* __restrict__ attn4)
{
    const int p = blockIdx.x;
    const int b = blockIdx.y;
    const int ks = blockIdx.z;
    const int i = p/3, j = p - 3*(p/3);
    const int tid = threadIdx.y*16 + threadIdx.x;

    __shared__ float Qs[16][102];
    __shared__ float Ks[16][102];

    float acc[6][6];
    #pragma unroll
    for (int r=0;r<6;r++)
        #pragma unroll
        for (int s=0;s<6;s++) acc[r][s]=0.f;

    const int lbase = ks*256;
    for (int l0 = lbase; l0 < lbase + 256; l0 += 16) {
        // 768 half2 loads = 16 kk x 48 ci2, 3 rounds of 256
        #pragma unroll
        for (int it = 0; it < 3; it++) {
            int e = tid + it*256;
            int kk = e & 15, cb = e >> 4;      // cb = ci2 (0..47)
            int l = l0 + kk;
            int gh = 3*(l>>5) + i, gw = 3*(l&31) + j;
            size_t off = ((size_t)(b*48 + cb))*HW + gh*WW + gw;
            __half2 hq = *(const __half2*)&qh[off];
            __half2 hk = *(const __half2*)&kh[off];
            Qs[kk][2*cb]   = __low2float(hq);
            Qs[kk][2*cb+1] = __high2float(hq);
            Ks[kk][2*cb]   = __low2float(hk);
            Ks[kk][2*cb+1] = __high2float(hk);
        }
        __syncthreads();
        #pragma unroll
        for (int k2=0; k2<16; k2++) {
            float rq[6], rk[6];
            #pragma unroll
            for (int r=0;r<6;r++) {
                rq[r] = Qs[k2][threadIdx.y*6 + r];
                rk[r] = Ks[k2][threadIdx.x*6 + r];
            }
            #pragma unroll
            for (int r=0;r<6;r++)
                #pragma unroll
                for (int s=0;s<6;s++)
                    acc[r][s] = fmaf(rq[r], rk[s], acc[r][s]);
        }
        __syncthreads();
    }
    #pragma unroll
    for (int r=0;r<6;r++)
        #pragma unroll
        for (int s=0;s<6;s++) {
            int cq = threadIdx.y*6 + r, ck = threadIdx.x*6 + s;
            attn4[((size_t)(ks*768 + b*CCH + ck))*864 + cq*9 + p] = acc[r][s];
        }
}

// ---------------- softmax + direct fragment-layout weight emit -------------
__global__ __launch_bounds__(256)
void softmax_kernel(const float* __restrict__ attn4, unsigned* __restrict__ wath)
{
    const int rowid = blockIdx.x;          // b*96 + ck
    const float scale = 0.034020690871988585f;   // 1/sqrt(864)
    const int tid = threadIdx.x;
    __shared__ float red[256];
    __shared__ float sm[864];

    float v[4];
    float mx = -1e30f;
    #pragma unroll
    for (int it=0; it<4; it++) {
        int idx = tid + it*256;
        float s = -1e30f;
        if (idx < 864) {
            s = 0.f;
            #pragma unroll
            for (int ks = 0; ks < NSPLIT; ks++)
                s += attn4[((size_t)(ks*768 + rowid))*864 + idx];
            s *= scale;
        }
        v[it] = s;
        mx = fmaxf(mx, s);
    }
    red[tid] = mx; __syncthreads();
    for (int s=128; s>0; s>>=1) { if (tid<s) red[tid]=fmaxf(red[tid],red[tid+s]); __syncthreads(); }
    mx = red[0]; __syncthreads();

    float sum = 0.f;
    #pragma unroll
    for (int it=0; it<4; it++) {
        int idx = tid + it*256;
        v[it] = (idx < 864) ? expf(v[it]-mx) : 0.f;
        sum += v[it];
    }
    red[tid] = sum; __syncthreads();
    for (int s=128; s>0; s>>=1) { if (tid<s) red[tid]+=red[tid+s]; __syncthreads(); }
    float inv = 1.f/red[0];
    __syncthreads();

    #pragma unroll
    for (int it=0; it<4; it++) {
        int idx = tid + it*256;
        if (idx < 864) sm[idx] = v[it]*inv;
    }
    __syncthreads();

    const int bb = rowid / CCH, ck = rowid - (rowid/CCH)*CCH;
    const int mt = ck >> 4, gq = ck & 7, hiw = (ck >> 3) & 1;
    #pragma unroll
    for (int it = 0; it < 2; it++) {
        int e = tid + it*256;
        if (e < 432) {
            int u = e / 9, tap = e - 9*u;
            int chunk = u >> 3, hi2 = (u & 7) >> 2, t = u & 3;
            int w = hiw | (hi2 << 1);
            int lane = (gq << 2) | t;
            wath[(size_t)bb*6*WCH2 + chunk*WCH2 + ((tap*6 + mt)*32 + lane)*4 + w] =
                packh2(sm[2*u*9 + tap], sm[(2*u + 1)*9 + tap]);
        }
    }
}

// ---------------- batchnorm statistics (biased var) ----------------
__global__ __launch_bounds__(256)
void bnstats_kernel(const float* __restrict__ y1, const float* __restrict__ y2,
                    const float* __restrict__ y3,
                    float* __restrict__ meanv, float* __restrict__ istdv)
{
    const int t = blockIdx.x / CCH, c = blockIdx.x - t*CCH;
    const float* src = (t==0) ? y1 : (t==1) ? y2 : y3;
    float s = 0.f, sq = 0.f;
    for (int e = threadIdx.x; e < BATCH*HW; e += 256) {
        int b = e / HW, hw = e - b*HW;
        float vv = src[((size_t)b*CCH + c)*HW + hw];
        s += vv; sq = fmaf(vv, vv, sq);
    }
    __shared__ float sh1[256], sh2[256];
    sh1[threadIdx.x]=s; sh2[threadIdx.x]=sq;
    __syncthreads();
    for (int st=128; st>0; st>>=1) {
        if (threadIdx.x < st) { sh1[threadIdx.x]+=sh1[threadIdx.x+st]; sh2[threadIdx.x]+=sh2[threadIdx.x+st]; }
        __syncthreads();
    }
    if (threadIdx.x==0) {
        const float invN = 1.f / (float)(BATCH*HW);
        float m = sh1[0]*invN;
        float var = sh2[0]*invN - m*m;
        meanv[blockIdx.x] = m;
        istdv[blockIdx.x] = rsqrtf(var + 1e-5f);
    }
}

// ---------------- final fuse: out = (x+y, x) ----------------
__global__ __launch_bounds__(256)
void finalize_kernel(const float* __restrict__ x1, const float* __restrict__ x2,
                     const float* __restrict__ y1, const float* __restrict__ y2,
                     const float* __restrict__ y3,
                     const float* __restrict__ meanv, const float* __restrict__ istdv,
                     float* __restrict__ out, int writeSecond)
{
    int idx = blockIdx.x*256 + threadIdx.x;
    if (idx >= N1OUT) return;
    int hw = idx % HW;
    int c  = (idx / HW) % (2*CCH);
    int b  = idx / (HW*2*CCH);
    float xv, yv;
    if (c < CCH) {
        size_t off = ((size_t)b*CCH + c)*HW + hw;
        xv = x1[off];
        float a = (y1[off]-meanv[c])       * istdv[c];
        float g = (y2[off]-meanv[CCH+c])   * istdv[CCH+c];
        yv = a*g;
    } else {
        int cc = c - CCH;
        size_t off = ((size_t)b*CCH + cc)*HW + hw;
        xv = x2[off];
        yv = (y3[off]-meanv[2*CCH+cc]) * istdv[2*CCH+cc];
    }
    out[idx] = xv + yv;
    if (writeSecond) out[N1OUT + idx] = xv;
}

// ---------------- launch ----------------
extern "C" void kernel_launch(void* const* d_in, const int* in_sizes, int n_in,
                              void* d_out, int out_size)
{
    const float* x1  = (const float*)d_in[0];
    const float* x2  = (const float*)d_in[1];
    const float* w1  = (const float*)d_in[2];
    const float* w2  = (const float*)d_in[3];
    const float* wa1 = (const float*)d_in[4];
    const float* wa2 = (const float*)d_in[5];
    const float* wa3 = (const float*)d_in[6];
    float* out = (float*)d_out;

    float *y1,*y2,*y3,*attn4,*meanv,*istdv;
    unsigned *x1h,*x2h,*qh,*kh,*vh,*w1h,*w2h,*wa1h,*wa2h,*wa3h,*wath;
    cudaGetSymbolAddress((void**)&y1,   g_y1);
    cudaGetSymbolAddress((void**)&y2,   g_y2);
    cudaGetSymbolAddress((void**)&y3,   g_y3);
    cudaGetSymbolAddress((void**)&attn4,g_attn4);
    cudaGetSymbolAddress((void**)&meanv,g_mean);
    cudaGetSymbolAddress((void**)&istdv,g_istd);
    cudaGetSymbolAddress((void**)&x1h,  g_x1h);
    cudaGetSymbolAddress((void**)&x2h,  g_x2h);
    cudaGetSymbolAddress((void**)&qh,   g_qh);
    cudaGetSymbolAddress((void**)&kh,   g_kh);
    cudaGetSymbolAddress((void**)&vh,   g_vh);
    cudaGetSymbolAddress((void**)&w1h,  g_w1h);
    cudaGetSymbolAddress((void**)&w2h,  g_w2h);
    cudaGetSymbolAddress((void**)&wa1h, g_wa1h);
    cudaGetSymbolAddress((void**)&wa2h, g_wa2h);
    cudaGetSymbolAddress((void**)&wa3h, g_wa3h);
    cudaGetSymbolAddress((void**)&wath, g_wath);

    static int smem_set = 0;
    const int CONV_SMEM = (2*WCH2 + 2*PBUF) * 4;   // 68096 B
    if (!smem_set) {
        cudaFuncSetAttribute(conv3x3_fp16_kernel,
                             cudaFuncAttributeMaxDynamicSharedMemorySize, CONV_SMEM);
        smem_set = 1;
    }

    // 1. inputs -> interleaved half2
    cvt_pair_kernel<<<dim3((NPIX2+255)/256, 2), 256>>>(x1, x1h, x2, x2h);

    // 2. all fixed weights -> fp16 fragment layout
    wprep_all_kernel<<<dim3((12*WCH2+255)/256, 5), 256>>>(
        w1, w2, wa1, wa2, wa3, w1h, w2h, wa1h, wa2h, wa3h);

    // 3. ALL five independent convs in one launch (q,k,v in half2 interleaved)
    {
        ConvJobs jb{};
        jb.j[0] = { x1h, x1h, w1h,  0, y1, 0,  0, 48, 48 };
        jb.j[1] = { x2h, x2h, w2h,  0, y2, 0,  0, 48, 48 };
        jb.j[2] = { x1h, x2h, wa1h, 0, 0,  qh, 1, 48, 96 };
        jb.j[3] = { x1h, x2h, wa2h, 0, 0,  kh, 1, 48, 96 };
        jb.j[4] = { x1h, x2h, wa3h, 0, 0,  vh, 1, 48, 96 };
        conv3x3_fp16_kernel<<<dim3(72, 5, 8), 192, CONV_SMEM>>>(jb);
    }

    // 4. attention logits (split-K x4, half2 inputs) + softmax -> conv weights
    attn_split_kernel<<<dim3(9, 8, NSPLIT), dim3(16,16)>>>(qh, kh, attn4);
    softmax_kernel<<<BATCH*CCH, 256>>>(attn4, wath);

    // 5. attn @ v_unf == per-batch 3x3 conv
    {
        ConvJobs jb{};
        jb.j[0] = { vh, vh, wath, 6L*WCH2, y3, 0, 0, 48, 48 };
        conv3x3_fp16_kernel<<<dim3(72, 1, 8), 192, CONV_SMEM>>>(jb);
    }

    // 6. batchnorm stats + fused epilogue
    bnstats_kernel<<<3*CCH, 256>>>(y1, y2, y3, meanv, istdv);
    int writeSecond = (out_size >= 2*N1OUT) ? 1 : 0;
    finalize_kernel<<<(N1OUT + 255)/256, 256>>>(x1, x2, y1, y2, y3, meanv, istdv, out, writeSecond);
}

// round 15
// speedup vs baseline: 1.1905x; 1.0951x over previous
#include <cuda_runtime.h>
#include <cuda_fp16.h>
#include <math.h>

#define BATCH 8
#define CCH 96
#define HH 96
#define WW 96
#define HW (HH*WW)                 // 9216
#define NPIX 7077888               // 8*96*96*96
#define NPIX2 (NPIX/2)
#define N1OUT 14155776             // 8*192*96*96
#define NSPLIT 4

#define WCH2  6912
#define PRS2  40
#define PCIS  400
#define PBUF  1600

// ---------------- scratch ----------------
__device__ float g_y1[NPIX];
__device__ float g_y2[NPIX];
__device__ float g_y3[NPIX];
__device__ float g_attn4[NSPLIT*BATCH*CCH*CCH*9];
__device__ float g_mean[3*CCH];
__device__ float g_istd[3*CCH];
__device__ float g_bnsum[3*CCH];
__device__ float g_bnsq [3*CCH];

__device__ __align__(16) unsigned g_x1h[NPIX2];
__device__ __align__(16) unsigned g_x2h[NPIX2];
__device__ __align__(16) unsigned g_qh [NPIX2];
__device__ __align__(16) unsigned g_kh [NPIX2];
__device__ __align__(16) unsigned g_vh [NPIX2];
__device__ __align__(16) unsigned g_w1h [6*WCH2];
__device__ __align__(16) unsigned g_w2h [6*WCH2];
__device__ __align__(16) unsigned g_wa1h[12*WCH2];
__device__ __align__(16) unsigned g_wa2h[12*WCH2];
__device__ __align__(16) unsigned g_wa3h[12*WCH2];
__device__ __align__(16) unsigned g_wath[BATCH*6*WCH2];

struct ConvJob {
    const unsigned* inA;
    const unsigned* inB;
    const unsigned* wh;
    long  wstride;
    float* outf;
    unsigned* outh;
    int outmode;      // 0=NCHW fp32, 1=interleaved half2
    int csplit2;
    int cin2;
    int statIdx;      // -1 = none; else BN stats row (0..2)
};
struct ConvJobs {
    ConvJob j[5];
};

__device__ __forceinline__ unsigned packh2(float a, float b) {
    __half2 h = __floats2half2_rn(a, b);
    return *(unsigned*)&h;
}

// ---------------- fp32 -> ci-pair-interleaved half2 ----------------
__global__ __launch_bounds__(256)
void cvt_pair_kernel(const float* __restrict__ s1, unsigned* __restrict__ d1,
                     const float* __restrict__ s2, unsigned* __restrict__ d2)
{
    const float* src = blockIdx.y ? s2 : s1;
    unsigned* dst    = blockIdx.y ? d2 : d1;
    int e = blockIdx.x*256 + threadIdx.x;
    if (e >= NPIX2) return;
    int b = e / (48*HW), r = e - b*48*HW;
    int ci2 = r / HW, hw = r - ci2*HW;
    size_t off = ((size_t)b*CCH + 2*ci2)*HW + hw;
    dst[e] = packh2(src[off], src[off + HW]);
}

// ---------------- weight pre-transform (+ zero BN stat buffers) ------------
__global__ __launch_bounds__(256)
void wprep_all_kernel(const float* __restrict__ w1, const float* __restrict__ w2,
                      const float* __restrict__ wa1, const float* __restrict__ wa2,
                      const float* __restrict__ wa3,
                      unsigned* __restrict__ d1, unsigned* __restrict__ d2,
                      unsigned* __restrict__ d3, unsigned* __restrict__ d4,
                      unsigned* __restrict__ d5)
{
    const int id = blockIdx.y;
    if (id == 0) {
        int z = blockIdx.x*256 + threadIdx.x;
        if (z < 3*CCH) { g_bnsum[z] = 0.f; g_bnsq[z] = 0.f; }
    }
    const float* src; unsigned* dst; int cin;
    if      (id == 0) { src = w1;  dst = d1; cin = 96;  }
    else if (id == 1) { src = w2;  dst = d2; cin = 96;  }
    else if (id == 2) { src = wa1; dst = d3; cin = 192; }
    else if (id == 3) { src = wa2; dst = d4; cin = 192; }
    else              { src = wa3; dst = d5; cin = 192; }
    const int nwords = (cin >> 4) * WCH2;
    int e = blockIdx.x*256 + threadIdx.x;
    if (e >= nwords) return;
    int chunk = e / WCH2, rm = e - chunk*WCH2;
    int w = rm & 3, lane = (rm >> 2) & 31, mtap = rm >> 7;
    int tap = mtap / 6, mt = mtap - 6*tap;
    int g = lane >> 2, t = lane & 3;
    int co = mt*16 + g + (w & 1)*8;
    int ci = chunk*16 + 2*t + ((w >> 1) & 1)*8;
    dst[e] = packh2(src[((size_t)co*cin + ci)*9 + tap],
                    src[((size_t)co*cin + ci + 1)*9 + tap]);
}

// ---------------- tensor-core 3x3 conv, fp16 m16n8k16, multi-job -----------
__global__ __launch_bounds__(192, 2)
void conv3x3_fp16_kernel(ConvJobs jobs)
{
    extern __shared__ unsigned dsm[];
    const ConvJob J = jobs.j[blockIdx.y];
    const unsigned* __restrict__ inAh = J.inA;
    const unsigned* __restrict__ inBh = J.inB;
    const int csplit2 = J.csplit2, cin2 = J.cin2;

    const int tid  = threadIdx.x;
    const int lane = tid & 31, wid = tid >> 5;
    const int g = lane >> 2, t = lane & 3;
    const int cog = wid >> 1;
    const int rp  = wid & 1;
    const int b   = blockIdx.z;
    const int byk = blockIdx.x / 6, bxk = blockIdx.x - 6*byk;
    const int by0 = byk*8, bx0 = bxk*16;

    const unsigned smem_b = (unsigned)__cvta_generic_to_shared(dsm);
    unsigned* psmem = dsm + 2*WCH2;

    int pgoff[8], psoff[8], pci[8];
    bool lok[8], sok[8];
    #pragma unroll
    for (int it = 0; it < 8; it++) {
        int e = tid + it*192;
        int ci = e / 180, r2 = e - ci*180;
        int row = r2 / 18, col = r2 - row*18;
        int gh = by0 + row - 1, gw = bx0 + col - 1;
        bool inp = (e < 1440);
        bool ok = inp && gh >= 0 && gh < HH && gw >= 0 && gw < WW;
        lok[it] = ok; sok[it] = inp;
        pgoff[it] = ok ? gh*WW + gw : 0;
        psoff[it] = inp ? (ci & 3)*PCIS + row*PRS2 + col*2 + (ci >> 2) : 0;
        pci[it]   = ci;
    }

    const unsigned* wsrc0 = J.wh + (size_t)J.wstride*b;

    #pragma unroll
    for (int k2 = 0; k2 < 9; k2++) {
        int idx = tid + k2*192;
        asm volatile("cp.async.cg.shared.global [%0], [%1], 16;"
                     :: "r"(smem_b + idx*16), "l"(wsrc0 + idx*4) : "memory");
    }
    asm volatile("cp.async.commit_group;" ::: "memory");
    {
        unsigned pv[8];
        #pragma unroll
        for (int it = 0; it < 8; it++) {
            int gci = pci[it];
            const unsigned* src = (gci < csplit2)
                ? inAh + ((size_t)b*csplit2 + gci)*HW
                : inBh + ((size_t)b*(cin2-csplit2) + (gci-csplit2))*HW;
            pv[it] = lok[it] ? src[pgoff[it]] : 0u;
        }
        #pragma unroll
        for (int it = 0; it < 8; it++)
            if (sok[it]) psmem[psoff[it]] = pv[it];
    }
    asm volatile("cp.async.wait_group 0;" ::: "memory");
    __syncthreads();

    float acc[2][8][4];
    #pragma unroll
    for (int m=0;m<2;m++)
        #pragma unroll
        for (int nt=0;nt<8;nt++)
            #pragma unroll
            for (int r=0;r<4;r++) acc[m][nt][r] = 0.f;

    const int nchunk = cin2 >> 3;
    for (int ch = 0; ch < nchunk; ch++) {
        const int cur = ch & 1;
        const bool more = (ch + 1 < nchunk);

        unsigned pv[8];
        if (more) {
            const unsigned* wsrc = wsrc0 + (size_t)(ch+1)*WCH2;
            const unsigned wdst = smem_b + (cur^1)*WCH2*4;
            #pragma unroll
            for (int k2 = 0; k2 < 9; k2++) {
                int idx = tid + k2*192;
                asm volatile("cp.async.cg.shared.global [%0], [%1], 16;"
                             :: "r"(wdst + idx*16), "l"(wsrc + idx*4) : "memory");
            }
            asm volatile("cp.async.commit_group;" ::: "memory");
            const int ci0 = (ch+1) << 3;
            #pragma unroll
            for (int it = 0; it < 8; it++) {
                int gci = ci0 + pci[it];
                const unsigned* src = (gci < csplit2)
                    ? inAh + ((size_t)b*csplit2 + gci)*HW
                    : inBh + ((size_t)b*(cin2-csplit2) + (gci-csplit2))*HW;
                pv[it] = lok[it] ? src[pgoff[it]] : 0u;
            }
        }

        const unsigned wbase = smem_b + cur*WCH2*4;
        const unsigned pbase = smem_b + (2*WCH2 + cur*PBUF)*4;
        #pragma unroll
        for (int tap = 0; tap < 9; tap++) {
            const int i = tap/3, j = tap - 3*(tap/3);
            unsigned a[2][4];
            #pragma unroll
            for (int m = 0; m < 2; m++) {
                const int mt = cog*2 + m;
                asm volatile("ld.shared.v4.b32 {%0,%1,%2,%3}, [%4];"
                    : "=r"(a[m][0]), "=r"(a[m][1]), "=r"(a[m][2]), "=r"(a[m][3])
                    : "r"(wbase + (((tap*6 + mt)*32 + lane)*16)));
            }
            #pragma unroll
            for (int nt = 0; nt < 8; nt++) {
                const int py = 4*rp + (nt & 3);
                const int cb2 = (nt >> 2) * 8;
                unsigned b0, b1;
                asm volatile("ld.shared.v2.b32 {%0,%1}, [%2];"
                    : "=r"(b0), "=r"(b1)
                    : "r"(pbase + (t*PCIS + (py+i)*PRS2 + (cb2+j+g)*2)*4));
                #pragma unroll
                for (int m = 0; m < 2; m++) {
                    asm volatile(
                        "mma.sync.aligned.m16n8k16.row.col.f32.f16.f16.f32 "
                        "{%0,%1,%2,%3}, {%4,%5,%6,%7}, {%8,%9}, {%0,%1,%2,%3};"
                        : "+f"(acc[m][nt][0]), "+f"(acc[m][nt][1]),
                          "+f"(acc[m][nt][2]), "+f"(acc[m][nt][3])
                        : "r"(a[m][0]), "r"(a[m][1]), "r"(a[m][2]), "r"(a[m][3]),
                          "r"(b0), "r"(b1));
                }
            }
        }

        if (more) {
            unsigned* pd = psmem + (cur^1)*PBUF;
            #pragma unroll
            for (int it = 0; it < 8; it++)
                if (sok[it]) pd[psoff[it]] = pv[it];
            asm volatile("cp.async.wait_group 0;" ::: "memory");
        }
        __syncthreads();
    }

    // ---- writeback ----
    if (J.outmode == 0) {
        float* out = J.outf;
        #pragma unroll
        for (int m = 0; m < 2; m++)
            #pragma unroll
            for (int nt = 0; nt < 8; nt++) {
                int co  = cog*32 + m*16 + g;
                int row = by0 + 4*rp + (nt & 3);
                int col = bx0 + (nt >> 2)*8 + 2*t;
                size_t base = (((size_t)b*CCH + co)*HH + row)*WW + col;
                *(float2*)&out[base]        = make_float2(acc[m][nt][0], acc[m][nt][1]);
                *(float2*)&out[base + 8*HW] = make_float2(acc[m][nt][2], acc[m][nt][3]);
            }
        // ---- fused BN statistics (per-channel sum / sumsq) ----
        if (J.statIdx >= 0) {
            #pragma unroll
            for (int m = 0; m < 2; m++) {
                float s0=0.f, q0=0.f, s1=0.f, q1=0.f;
                #pragma unroll
                for (int nt = 0; nt < 8; nt++) {
                    float a0 = acc[m][nt][0], a1 = acc[m][nt][1];
                    float a2 = acc[m][nt][2], a3 = acc[m][nt][3];
                    s0 += a0 + a1;  q0 = fmaf(a0,a0,fmaf(a1,a1,q0));
                    s1 += a2 + a3;  q1 = fmaf(a2,a2,fmaf(a3,a3,q1));
                }
                s0 += __shfl_xor_sync(0xFFFFFFFFu, s0, 1);
                s0 += __shfl_xor_sync(0xFFFFFFFFu, s0, 2);
                q0 += __shfl_xor_sync(0xFFFFFFFFu, q0, 1);
                q0 += __shfl_xor_sync(0xFFFFFFFFu, q0, 2);
                s1 += __shfl_xor_sync(0xFFFFFFFFu, s1, 1);
                s1 += __shfl_xor_sync(0xFFFFFFFFu, s1, 2);
                q1 += __shfl_xor_sync(0xFFFFFFFFu, q1, 1);
                q1 += __shfl_xor_sync(0xFFFFFFFFu, q1, 2);
                if (t == 0) {
                    int co = cog*32 + m*16 + g;
                    atomicAdd(&g_bnsum[J.statIdx*CCH + co],     s0);
                    atomicAdd(&g_bnsq [J.statIdx*CCH + co],     q0);
                    atomicAdd(&g_bnsum[J.statIdx*CCH + co + 8], s1);
                    atomicAdd(&g_bnsq [J.statIdx*CCH + co + 8], q1);
                }
            }
        }
    } else {
        unsigned* outh = J.outh;
        #pragma unroll
        for (int m = 0; m < 2; m++)
            #pragma unroll
            for (int nt = 0; nt < 8; nt++) {
                float a0 = acc[m][nt][0], a1 = acc[m][nt][1];
                float a2 = acc[m][nt][2], a3 = acc[m][nt][3];
                float p0 = __shfl_xor_sync(0xFFFFFFFFu, a0, 4);
                float p1 = __shfl_xor_sync(0xFFFFFFFFu, a1, 4);
                float p2 = __shfl_xor_sync(0xFFFFFFFFu, a2, 4);
                float p3 = __shfl_xor_sync(0xFFFFFFFFu, a3, 4);
                int row = by0 + 4*rp + (nt & 3);
                int col = bx0 + (nt >> 2)*8 + 2*t;
                int B = cog*32 + m*16;
                int ci2; unsigned w0, w1;
                if ((g & 1) == 0) {
                    ci2 = (B >> 1) + (g >> 1);
                    w0 = packh2(a0, p0); w1 = packh2(a1, p1);
                } else {
                    ci2 = (B >> 1) + 4 + ((g - 1) >> 1);
                    w0 = packh2(p2, a2); w1 = packh2(p3, a3);
                }
                *(uint2*)&outh[((size_t)b*48 + ci2)*HW + row*WW + col] =
                    make_uint2(w0, w1);
            }
    }
}

// ---------------- attention GEMM, split-K x4, half2 q/k ----------------
__global__ __launch_bounds__(256)
void attn_split_kernel(const unsigned* __restrict__ qh, const unsigned* __restrict__ kh,
                       float* __restrict__ attn4)
{
    const int p = blockIdx.x;
    const int b = blockIdx.y;
    const int ks = blockIdx.z;
    const int i = p/3, j = p - 3*(p/3);
    const int tid = threadIdx.y*16 + threadIdx.x;

    __shared__ float Qs[16][102];
    __shared__ float Ks[16][102];

    float acc[6][6];
    #pragma unroll
    for (int r=0;r<6;r++)
        #pragma unroll
        for (int s=0;s<6;s++) acc[r][s]=0.f;

    const int lbase = ks*256;
    for (int l0 = lbase; l0 < lbase + 256; l0 += 16) {
        #pragma unroll
        for (int it = 0; it < 3; it++) {
            int e = tid + it*256;
            int kk = e & 15, cb = e >> 4;
            int l = l0 + kk;
            int gh = 3*(l>>5) + i, gw = 3*(l&31) + j;
            size_t off = ((size_t)(b*48 + cb))*HW + gh*WW + gw;
            __half2 hq = *(const __half2*)&qh[off];
            __half2 hk = *(const __half2*)&kh[off];
            Qs[kk][2*cb]   = __low2float(hq);
            Qs[kk][2*cb+1] = __high2float(hq);
            Ks[kk][2*cb]   = __low2float(hk);
            Ks[kk][2*cb+1] = __high2float(hk);
        }
        __syncthreads();
        #pragma unroll
        for (int k2=0; k2<16; k2++) {
            float rq[6], rk[6];
            #pragma unroll
            for (int r=0;r<6;r++) {
                rq[r] = Qs[k2][threadIdx.y*6 + r];
                rk[r] = Ks[k2][threadIdx.x*6 + r];
            }
            #pragma unroll
            for (int r=0;r<6;r++)
                #pragma unroll
                for (int s=0;s<6;s++)
                    acc[r][s] = fmaf(rq[r], rk[s], acc[r][s]);
        }
        __syncthreads();
    }
    #pragma unroll
    for (int r=0;r<6;r++)
        #pragma unroll
        for (int s=0;s<6;s++) {
            int cq = threadIdx.y*6 + r, ck = threadIdx.x*6 + s;
            attn4[((size_t)(ks*768 + b*CCH + ck))*864 + cq*9 + p] = acc[r][s];
        }
}

// ---------------- softmax + direct fragment-layout weight emit -------------
__global__ __launch_bounds__(256)
void softmax_kernel(const float* __restrict__ attn4, unsigned* __restrict__ wath)
{
    const int rowid = blockIdx.x;
    const float scale = 0.034020690871988585f;   // 1/sqrt(864)
    const int tid = threadIdx.x;
    __shared__ float red[256];
    __shared__ float sm[864];

    float v[4];
    float mx = -1e30f;
    #pragma unroll
    for (int it=0; it<4; it++) {
        int idx = tid + it*256;
        float s = -1e30f;
        if (idx < 864) {
            s = 0.f;
            #pragma unroll
            for (int ks = 0; ks < NSPLIT; ks++)
                s += attn4[((size_t)(ks*768 + rowid))*864 + idx];
            s *= scale;
        }
        v[it] = s;
        mx = fmaxf(mx, s);
    }
    red[tid] = mx; __syncthreads();
    for (int s=128; s>0; s>>=1) { if (tid<s) red[tid]=fmaxf(red[tid],red[tid+s]); __syncthreads(); }
    mx = red[0]; __syncthreads();

    float sum = 0.f;
    #pragma unroll
    for (int it=0; it<4; it++) {
        int idx = tid + it*256;
        v[it] = (idx < 864) ? expf(v[it]-mx) : 0.f;
        sum += v[it];
    }
    red[tid] = sum; __syncthreads();
    for (int s=128; s>0; s>>=1) { if (tid<s) red[tid]+=red[tid+s]; __syncthreads(); }
    float inv = 1.f/red[0];
    __syncthreads();

    #pragma unroll
    for (int it=0; it<4; it++) {
        int idx = tid + it*256;
        if (idx < 864) sm[idx] = v[it]*inv;
    }
    __syncthreads();

    const int bb = rowid / CCH, ck = rowid - (rowid/CCH)*CCH;
    const int mt = ck >> 4, gq = ck & 7, hiw = (ck >> 3) & 1;
    #pragma unroll
    for (int it = 0; it < 2; it++) {
        int e = tid + it*256;
        if (e < 432) {
            int u = e / 9, tap = e - 9*u;
            int chunk = u >> 3, hi2 = (u & 7) >> 2, t = u & 3;
            int w = hiw | (hi2 << 1);
            int lane = (gq << 2) | t;
            wath[(size_t)bb*6*WCH2 + chunk*WCH2 + ((tap*6 + mt)*32 + lane)*4 + w] =
                packh2(sm[2*u*9 + tap], sm[(2*u + 1)*9 + tap]);
        }
    }
}

// ---------------- BN finalize: sums -> mean/istd ----------------
__global__ void bnfinal_kernel()
{
    int e = threadIdx.x;
    if (e >= 3*CCH) return;
    const float invN = 1.f / (float)(BATCH*HW);
    float m = g_bnsum[e] * invN;
    float var = g_bnsq[e] * invN - m*m;
    g_mean[e] = m;
    g_istd[e] = rsqrtf(var + 1e-5f);
}

// ---------------- final fuse (vectorized float4) ----------------
// grid (9, 192, 8), 256 thr, 4 floats/thread
__global__ __launch_bounds__(256)
void finalize_kernel(const float* __restrict__ x1, const float* __restrict__ x2,
                     const float* __restrict__ y1, const float* __restrict__ y2,
                     const float* __restrict__ y3,
                     float* __restrict__ out, int writeSecond)
{
    const int hw = blockIdx.x*1024 + threadIdx.x*4;
    const int c  = blockIdx.y;
    const int b  = blockIdx.z;
    size_t oidx = ((size_t)b*2*CCH + c)*HW + hw;
    float4 xv, yv;
    if (c < CCH) {
        size_t off = ((size_t)b*CCH + c)*HW + hw;
        xv = *(const float4*)&x1[off];
        float4 a = *(const float4*)&y1[off];
        float4 g4 = *(const float4*)&y2[off];
        float m1 = g_mean[c],       s1 = g_istd[c];
        float m2 = g_mean[CCH+c],   s2 = g_istd[CCH+c];
        yv.x = ((a.x-m1)*s1)*((g4.x-m2)*s2);
        yv.y = ((a.y-m1)*s1)*((g4.y-m2)*s2);
        yv.z = ((a.z-m1)*s1)*((g4.z-m2)*s2);
        yv.w = ((a.w-m1)*s1)*((g4.w-m2)*s2);
    } else {
        int cc = c - CCH;
        size_t off = ((size_t)b*CCH + cc)*HW + hw;
        xv = *(const float4*)&x2[off];
        float4 a = *(const float4*)&y3[off];
        float m3 = g_mean[2*CCH+cc], s3 = g_istd[2*CCH+cc];
        yv.x = (a.x-m3)*s3; yv.y = (a.y-m3)*s3;
        yv.z = (a.z-m3)*s3; yv.w = (a.w-m3)*s3;
    }
    float4 o;
    o.x = xv.x + yv.x; o.y = xv.y + yv.y;
    o.z = xv.z + yv.z; o.w = xv.w + yv.w;
    *(float4*)&out[oidx] = o;
    if (writeSecond) *(float4*)&out[N1OUT + oidx] = xv;
}

// ---------------- launch ----------------
extern "C" void kernel_launch(void* const* d_in, const int* in_sizes, int n_in,
                              void* d_out, int out_size)
{
    const float* x1  = (const float*)d_in[0];
    const float* x2  = (const float*)d_in[1];
    const float* w1  = (const float*)d_in[2];
    const float* w2  = (const float*)d_in[3];
    const float* wa1 = (const float*)d_in[4];
    const float* wa2 = (const float*)d_in[5];
    const float* wa3 = (const float*)d_in[6];
    float* out = (float*)d_out;

    float *y1,*y2,*y3,*attn4;
    unsigned *x1h,*x2h,*qh,*kh,*vh,*w1h,*w2h,*wa1h,*wa2h,*wa3h,*wath;
    cudaGetSymbolAddress((void**)&y1,   g_y1);
    cudaGetSymbolAddress((void**)&y2,   g_y2);
    cudaGetSymbolAddress((void**)&y3,   g_y3);
    cudaGetSymbolAddress((void**)&attn4,g_attn4);
    cudaGetSymbolAddress((void**)&x1h,  g_x1h);
    cudaGetSymbolAddress((void**)&x2h,  g_x2h);
    cudaGetSymbolAddress((void**)&qh,   g_qh);
    cudaGetSymbolAddress((void**)&kh,   g_kh);
    cudaGetSymbolAddress((void**)&vh,   g_vh);
    cudaGetSymbolAddress((void**)&w1h,  g_w1h);
    cudaGetSymbolAddress((void**)&w2h,  g_w2h);
    cudaGetSymbolAddress((void**)&wa1h, g_wa1h);
    cudaGetSymbolAddress((void**)&wa2h, g_wa2h);
    cudaGetSymbolAddress((void**)&wa3h, g_wa3h);
    cudaGetSymbolAddress((void**)&wath, g_wath);

    static int smem_set = 0;
    const int CONV_SMEM = (2*WCH2 + 2*PBUF) * 4;   // 68096 B
    if (!smem_set) {
        cudaFuncSetAttribute(conv3x3_fp16_kernel,
                             cudaFuncAttributeMaxDynamicSharedMemorySize, CONV_SMEM);
        smem_set = 1;
    }

    // 1. inputs -> interleaved half2
    cvt_pair_kernel<<<dim3((NPIX2+255)/256, 2), 256>>>(x1, x1h, x2, x2h);

    // 2. weights -> fragment layout; zero BN stat buffers
    wprep_all_kernel<<<dim3((12*WCH2+255)/256, 5), 256>>>(
        w1, w2, wa1, wa2, wa3, w1h, w2h, wa1h, wa2h, wa3h);

    // 3. five convs in one launch; y1/y2 accumulate BN stats in epilogue
    {
        ConvJobs jb{};
        jb.j[0] = { x1h, x1h, w1h,  0, y1, 0,  0, 48, 48, 0 };
        jb.j[1] = { x2h, x2h, w2h,  0, y2, 0,  0, 48, 48, 1 };
        jb.j[2] = { x1h, x2h, wa1h, 0, 0,  qh, 1, 48, 96, -1 };
        jb.j[3] = { x1h, x2h, wa2h, 0, 0,  kh, 1, 48, 96, -1 };
        jb.j[4] = { x1h, x2h, wa3h, 0, 0,  vh, 1, 48, 96, -1 };
        conv3x3_fp16_kernel<<<dim3(72, 5, 8), 192, CONV_SMEM>>>(jb);
    }

    // 4. attention logits + softmax -> y3-conv weights
    attn_split_kernel<<<dim3(9, 8, NSPLIT), dim3(16,16)>>>(qh, kh, attn4);
    softmax_kernel<<<BATCH*CCH, 256>>>(attn4, wath);

    // 5. attn @ v_unf == per-batch conv; y3 stats fused
    {
        ConvJobs jb{};
        jb.j[0] = { vh, vh, wath, 6L*WCH2, y3, 0, 0, 48, 48, 2 };
        conv3x3_fp16_kernel<<<dim3(72, 1, 8), 192, CONV_SMEM>>>(jb);
    }

    // 6. BN mean/istd + fused epilogue
    bnfinal_kernel<<<1, 3*CCH>>>();
    int writeSecond = (out_size >= 2*N1OUT) ? 1 : 0;
    finalize_kernel<<<dim3(9, 2*CCH, BATCH), 256>>>(x1, x2, y1, y2, y3, out, writeSecond);
}

// round 16
// speedup vs baseline: 1.2619x; 1.0600x over previous
#include <cuda_runtime.h>
#include <cuda_fp16.h>
#include <math.h>

#define BATCH 8
#define CCH 96
#define HH 96
#define WW 96
#define HW (HH*WW)                 // 9216
#define NPIX 7077888               // 8*96*96*96
#define NPIX2 (NPIX/2)
#define N1OUT 14155776             // 8*192*96*96
#define NSPLIT 4

#define WCH2  6912
#define PRS2  40
#define PCIS  400
#define PBUF  1600

// ---------------- scratch ----------------
__device__ float g_y1[NPIX];
__device__ float g_y2[NPIX];
__device__ float g_y3[NPIX];
__device__ float g_attn4[NSPLIT*BATCH*CCH*CCH*9];
__device__ float g_mean[3*CCH];
__device__ float g_istd[3*CCH];
__device__ float g_bnsum[3*CCH];
__device__ float g_bnsq [3*CCH];

__device__ __align__(16) unsigned g_x1h[NPIX2];
__device__ __align__(16) unsigned g_x2h[NPIX2];
__device__ __align__(16) unsigned g_qh [NPIX2];
__device__ __align__(16) unsigned g_kh [NPIX2];
__device__ __align__(16) unsigned g_vh [NPIX2];
__device__ __align__(16) unsigned g_w1h [6*WCH2];
__device__ __align__(16) unsigned g_w2h [6*WCH2];
__device__ __align__(16) unsigned g_wa1h[12*WCH2];
__device__ __align__(16) unsigned g_wa2h[12*WCH2];
__device__ __align__(16) unsigned g_wa3h[12*WCH2];
__device__ __align__(16) unsigned g_wath[BATCH*6*WCH2];

struct ConvJob {
    const unsigned* inA;
    const unsigned* inB;
    const unsigned* wh;
    long  wstride;
    float* outf;
    unsigned* outh;
    int outmode;      // 0=NCHW fp32, 1=interleaved half2
    int csplit2;
    int cin2;
    int statIdx;      // -1 = none; else BN stats row (0..2)
};
struct ConvJobs {
    ConvJob j[5];
};

__device__ __forceinline__ unsigned packh2(float a, float b) {
    __half2 h = __floats2half2_rn(a, b);
    return *(unsigned*)&h;
}

// ---------------- fp32 -> ci-pair-interleaved half2 ----------------
__global__ __launch_bounds__(256)
void cvt_pair_kernel(const float* __restrict__ s1, unsigned* __restrict__ d1,
                     const float* __restrict__ s2, unsigned* __restrict__ d2)
{
    const float* src = blockIdx.y ? s2 : s1;
    unsigned* dst    = blockIdx.y ? d2 : d1;
    int e = blockIdx.x*256 + threadIdx.x;
    if (e >= NPIX2) return;
    int b = e / (48*HW), r = e - b*48*HW;
    int ci2 = r / HW, hw = r - ci2*HW;
    size_t off = ((size_t)b*CCH + 2*ci2)*HW + hw;
    dst[e] = packh2(src[off], src[off + HW]);
}

// ---------------- weight pre-transform (+ zero BN stat buffers) ------------
__global__ __launch_bounds__(256)
void wprep_all_kernel(const float* __restrict__ w1, const float* __restrict__ w2,
                      const float* __restrict__ wa1, const float* __restrict__ wa2,
                      const float* __restrict__ wa3,
                      unsigned* __restrict__ d1, unsigned* __restrict__ d2,
                      unsigned* __restrict__ d3, unsigned* __restrict__ d4,
                      unsigned* __restrict__ d5)
{
    const int id = blockIdx.y;
    if (id == 0) {
        int z = blockIdx.x*256 + threadIdx.x;
        if (z < 3*CCH) { g_bnsum[z] = 0.f; g_bnsq[z] = 0.f; }
    }
    const float* src; unsigned* dst; int cin;
    if      (id == 0) { src = w1;  dst = d1; cin = 96;  }
    else if (id == 1) { src = w2;  dst = d2; cin = 96;  }
    else if (id == 2) { src = wa1; dst = d3; cin = 192; }
    else if (id == 3) { src = wa2; dst = d4; cin = 192; }
    else              { src = wa3; dst = d5; cin = 192; }
    const int nwords = (cin >> 4) * WCH2;
    int e = blockIdx.x*256 + threadIdx.x;
    if (e >= nwords) return;
    int chunk = e / WCH2, rm = e - chunk*WCH2;
    int w = rm & 3, lane = (rm >> 2) & 31, mtap = rm >> 7;
    int tap = mtap / 6, mt = mtap - 6*tap;
    int g = lane >> 2, t = lane & 3;
    int co = mt*16 + g + (w & 1)*8;
    int ci = chunk*16 + 2*t + ((w >> 1) & 1)*8;
    dst[e] = packh2(src[((size_t)co*cin + ci)*9 + tap],
                    src[((size_t)co*cin + ci + 1)*9 + tap]);
}

// ---------------- tensor-core 3x3 conv, fp16 m16n8k16, multi-job -----------
__global__ __launch_bounds__(192, 2)
void conv3x3_fp16_kernel(ConvJobs jobs)
{
    extern __shared__ unsigned dsm[];
    const ConvJob J = jobs.j[blockIdx.y];
    const unsigned* __restrict__ inAh = J.inA;
    const unsigned* __restrict__ inBh = J.inB;
    const int csplit2 = J.csplit2, cin2 = J.cin2;

    const int tid  = threadIdx.x;
    const int lane = tid & 31, wid = tid >> 5;
    const int g = lane >> 2, t = lane & 3;
    const int cog = wid >> 1;
    const int rp  = wid & 1;
    const int b   = blockIdx.z;
    const int byk = blockIdx.x / 6, bxk = blockIdx.x - 6*byk;
    const int by0 = byk*8, bx0 = bxk*16;

    const unsigned smem_b = (unsigned)__cvta_generic_to_shared(dsm);
    unsigned* psmem = dsm + 2*WCH2;

    int pgoff[8], psoff[8], pci[8];
    bool lok[8], sok[8];
    #pragma unroll
    for (int it = 0; it < 8; it++) {
        int e = tid + it*192;
        int ci = e / 180, r2 = e - ci*180;
        int row = r2 / 18, col = r2 - row*18;
        int gh = by0 + row - 1, gw = bx0 + col - 1;
        bool inp = (e < 1440);
        bool ok = inp && gh >= 0 && gh < HH && gw >= 0 && gw < WW;
        lok[it] = ok; sok[it] = inp;
        pgoff[it] = ok ? gh*WW + gw : 0;
        psoff[it] = inp ? (ci & 3)*PCIS + row*PRS2 + col*2 + (ci >> 2) : 0;
        pci[it]   = ci;
    }

    const unsigned* wsrc0 = J.wh + (size_t)J.wstride*b;

    #pragma unroll
    for (int k2 = 0; k2 < 9; k2++) {
        int idx = tid + k2*192;
        asm volatile("cp.async.cg.shared.global [%0], [%1], 16;"
                     :: "r"(smem_b + idx*16), "l"(wsrc0 + idx*4) : "memory");
    }
    asm volatile("cp.async.commit_group;" ::: "memory");
    {
        unsigned pv[8];
        #pragma unroll
        for (int it = 0; it < 8; it++) {
            int gci = pci[it];
            const unsigned* src = (gci < csplit2)
                ? inAh + ((size_t)b*csplit2 + gci)*HW
                : inBh + ((size_t)b*(cin2-csplit2) + (gci-csplit2))*HW;
            pv[it] = lok[it] ? src[pgoff[it]] : 0u;
        }
        #pragma unroll
        for (int it = 0; it < 8; it++)
            if (sok[it]) psmem[psoff[it]] = pv[it];
    }
    asm volatile("cp.async.wait_group 0;" ::: "memory");
    __syncthreads();

    float acc[2][8][4];
    #pragma unroll
    for (int m=0;m<2;m++)
        #pragma unroll
        for (int nt=0;nt<8;nt++)
            #pragma unroll
            for (int r=0;r<4;r++) acc[m][nt][r] = 0.f;

    const int nchunk = cin2 >> 3;
    for (int ch = 0; ch < nchunk; ch++) {
        const int cur = ch & 1;
        const bool more = (ch + 1 < nchunk);

        unsigned pv[8];
        if (more) {
            const unsigned* wsrc = wsrc0 + (size_t)(ch+1)*WCH2;
            const unsigned wdst = smem_b + (cur^1)*WCH2*4;
            #pragma unroll
            for (int k2 = 0; k2 < 9; k2++) {
                int idx = tid + k2*192;
                asm volatile("cp.async.cg.shared.global [%0], [%1], 16;"
                             :: "r"(wdst + idx*16), "l"(wsrc + idx*4) : "memory");
            }
            asm volatile("cp.async.commit_group;" ::: "memory");
            const int ci0 = (ch+1) << 3;
            #pragma unroll
            for (int it = 0; it < 8; it++) {
                int gci = ci0 + pci[it];
                const unsigned* src = (gci < csplit2)
                    ? inAh + ((size_t)b*csplit2 + gci)*HW
                    : inBh + ((size_t)b*(cin2-csplit2) + (gci-csplit2))*HW;
                pv[it] = lok[it] ? src[pgoff[it]] : 0u;
            }
        }

        const unsigned wbase = smem_b + cur*WCH2*4;
        const unsigned pbase = smem_b + (2*WCH2 + cur*PBUF)*4;
        #pragma unroll
        for (int tap = 0; tap < 9; tap++) {
            const int i = tap/3, j = tap - 3*(tap/3);
            unsigned a[2][4];
            #pragma unroll
            for (int m = 0; m < 2; m++) {
                const int mt = cog*2 + m;
                asm volatile("ld.shared.v4.b32 {%0,%1,%2,%3}, [%4];"
                    : "=r"(a[m][0]), "=r"(a[m][1]), "=r"(a[m][2]), "=r"(a[m][3])
                    : "r"(wbase + (((tap*6 + mt)*32 + lane)*16)));
            }
            #pragma unroll
            for (int nt = 0; nt < 8; nt++) {
                const int py = 4*rp + (nt & 3);
                const int cb2 = (nt >> 2) * 8;
                unsigned b0, b1;
                asm volatile("ld.shared.v2.b32 {%0,%1}, [%2];"
                    : "=r"(b0), "=r"(b1)
                    : "r"(pbase + (t*PCIS + (py+i)*PRS2 + (cb2+j+g)*2)*4));
                #pragma unroll
                for (int m = 0; m < 2; m++) {
                    asm volatile(
                        "mma.sync.aligned.m16n8k16.row.col.f32.f16.f16.f32 "
                        "{%0,%1,%2,%3}, {%4,%5,%6,%7}, {%8,%9}, {%0,%1,%2,%3};"
                        : "+f"(acc[m][nt][0]), "+f"(acc[m][nt][1]),
                          "+f"(acc[m][nt][2]), "+f"(acc[m][nt][3])
                        : "r"(a[m][0]), "r"(a[m][1]), "r"(a[m][2]), "r"(a[m][3]),
                          "r"(b0), "r"(b1));
                }
            }
        }

        if (more) {
            unsigned* pd = psmem + (cur^1)*PBUF;
            #pragma unroll
            for (int it = 0; it < 8; it++)
                if (sok[it]) pd[psoff[it]] = pv[it];
            asm volatile("cp.async.wait_group 0;" ::: "memory");
        }
        __syncthreads();
    }

    // ---- writeback ----
    if (J.outmode == 0) {
        float* out = J.outf;
        #pragma unroll
        for (int m = 0; m < 2; m++)
            #pragma unroll
            for (int nt = 0; nt < 8; nt++) {
                int co  = cog*32 + m*16 + g;
                int row = by0 + 4*rp + (nt & 3);
                int col = bx0 + (nt >> 2)*8 + 2*t;
                size_t base = (((size_t)b*CCH + co)*HH + row)*WW + col;
                *(float2*)&out[base]        = make_float2(acc[m][nt][0], acc[m][nt][1]);
                *(float2*)&out[base + 8*HW] = make_float2(acc[m][nt][2], acc[m][nt][3]);
            }
        if (J.statIdx >= 0) {
            #pragma unroll
            for (int m = 0; m < 2; m++) {
                float s0=0.f, q0=0.f, s1=0.f, q1=0.f;
                #pragma unroll
                for (int nt = 0; nt < 8; nt++) {
                    float a0 = acc[m][nt][0], a1 = acc[m][nt][1];
                    float a2 = acc[m][nt][2], a3 = acc[m][nt][3];
                    s0 += a0 + a1;  q0 = fmaf(a0,a0,fmaf(a1,a1,q0));
                    s1 += a2 + a3;  q1 = fmaf(a2,a2,fmaf(a3,a3,q1));
                }
                s0 += __shfl_xor_sync(0xFFFFFFFFu, s0, 1);
                s0 += __shfl_xor_sync(0xFFFFFFFFu, s0, 2);
                q0 += __shfl_xor_sync(0xFFFFFFFFu, q0, 1);
                q0 += __shfl_xor_sync(0xFFFFFFFFu, q0, 2);
                s1 += __shfl_xor_sync(0xFFFFFFFFu, s1, 1);
                s1 += __shfl_xor_sync(0xFFFFFFFFu, s1, 2);
                q1 += __shfl_xor_sync(0xFFFFFFFFu, q1, 1);
                q1 += __shfl_xor_sync(0xFFFFFFFFu, q1, 2);
                if (t == 0) {
                    int co = cog*32 + m*16 + g;
                    atomicAdd(&g_bnsum[J.statIdx*CCH + co],     s0);
                    atomicAdd(&g_bnsq [J.statIdx*CCH + co],     q0);
                    atomicAdd(&g_bnsum[J.statIdx*CCH + co + 8], s1);
                    atomicAdd(&g_bnsq [J.statIdx*CCH + co + 8], q1);
                }
            }
        }
    } else {
        unsigned* outh = J.outh;
        #pragma unroll
        for (int m = 0; m < 2; m++)
            #pragma unroll
            for (int nt = 0; nt < 8; nt++) {
                float a0 = acc[m][nt][0], a1 = acc[m][nt][1];
                float a2 = acc[m][nt][2], a3 = acc[m][nt][3];
                float p0 = __shfl_xor_sync(0xFFFFFFFFu, a0, 4);
                float p1 = __shfl_xor_sync(0xFFFFFFFFu, a1, 4);
                float p2 = __shfl_xor_sync(0xFFFFFFFFu, a2, 4);
                float p3 = __shfl_xor_sync(0xFFFFFFFFu, a3, 4);
                int row = by0 + 4*rp + (nt & 3);
                int col = bx0 + (nt >> 2)*8 + 2*t;
                int B = cog*32 + m*16;
                int ci2; unsigned w0, w1;
                if ((g & 1) == 0) {
                    ci2 = (B >> 1) + (g >> 1);
                    w0 = packh2(a0, p0); w1 = packh2(a1, p1);
                } else {
                    ci2 = (B >> 1) + 4 + ((g - 1) >> 1);
                    w0 = packh2(p2, a2); w1 = packh2(p3, a3);
                }
                *(uint2*)&outh[((size_t)b*48 + ci2)*HW + row*WW + col] =
                    make_uint2(w0, w1);
            }
    }
}

// ---------------- attention logits on tensor cores ----------------
// grid (9, 8, NSPLIT), 256 thr (8 warps: 2 mwarps x 4 nwarps).
// Per block: 96cq x 96ck over 256 lattice kk (16 steps of k16).
// Qs/Ks tiles: [row][kk16] fp16, row stride 18 halves (9 words).
__global__ __launch_bounds__(256)
void attn_mma_kernel(const unsigned* __restrict__ qh, const unsigned* __restrict__ kh,
                     float* __restrict__ attn4)
{
    const int p = blockIdx.x;
    const int b = blockIdx.y;
    const int ks = blockIdx.z;
    const int i = p/3, j = p - 3*(p/3);
    const int tid = threadIdx.x;
    const int lane = tid & 31, wid = tid >> 5;
    const int g = lane >> 2, t = lane & 3;
    const int mw = wid >> 2, nw = wid & 3;

    __shared__ __half Qs[2][96*18];
    __shared__ __half Ks[2][96*18];

    float acc[3][3][4];
    #pragma unroll
    for (int mi=0;mi<3;mi++)
        #pragma unroll
        for (int ni=0;ni<3;ni++)
            #pragma unroll
            for (int r=0;r<4;r++) acc[mi][ni][r] = 0.f;

    // staging geometry: e = tid + r*256; ci2 = e>>4, kk = e&15
    int sci2[3], skk[3];
    #pragma unroll
    for (int r = 0; r < 3; r++) { int e = tid + r*256; sci2[r] = e >> 4; skk[r] = e & 15; }

    const unsigned* qb = qh + (size_t)b*48*HW;
    const unsigned* kb = kh + (size_t)b*48*HW;
    const int l0 = ks*256;

    // prologue: stage step 0 into buf 0
    {
        unsigned pq[3], pk[3];
        #pragma unroll
        for (int r = 0; r < 3; r++) {
            int l = l0 + skk[r];
            int a = (3*(l>>5) + i)*WW + 3*(l&31) + j;
            pq[r] = qb[(size_t)sci2[r]*HW + a];
            pk[r] = kb[(size_t)sci2[r]*HW + a];
        }
        #pragma unroll
        for (int r = 0; r < 3; r++) {
            __half2 hq = *(__half2*)&pq[r];
            __half2 hk = *(__half2*)&pk[r];
            Qs[0][(2*sci2[r])*18 + skk[r]]     = __low2half(hq);
            Qs[0][(2*sci2[r]+1)*18 + skk[r]]   = __high2half(hq);
            Ks[0][(2*sci2[r])*18 + skk[r]]     = __low2half(hk);
            Ks[0][(2*sci2[r]+1)*18 + skk[r]]   = __high2half(hk);
        }
    }
    __syncthreads();

    for (int step = 0; step < 16; step++) {
        const int cur = step & 1;
        const bool more = (step < 15);

        // prefetch next step's gather into registers
        unsigned pq[3], pk[3];
        if (more) {
            int lb = l0 + (step+1)*16;
            #pragma unroll
            for (int r = 0; r < 3; r++) {
                int l = lb + skk[r];
                int a = (3*(l>>5) + i)*WW + 3*(l&31) + j;
                pq[r] = qb[(size_t)sci2[r]*HW + a];
                pk[r] = kb[(size_t)sci2[r]*HW + a];
            }
        }

        // fragments + mma on current buffers
        const unsigned* Q2 = (const unsigned*)Qs[cur];
        const unsigned* K2 = (const unsigned*)Ks[cur];
        unsigned af[3][4], bf[3][2];
        #pragma unroll
        for (int mi = 0; mi < 3; mi++) {
            int r0 = mw*48 + mi*16 + g;
            af[mi][0] = Q2[r0*9 + t];
            af[mi][1] = Q2[(r0+8)*9 + t];
            af[mi][2] = Q2[r0*9 + t + 4];
            af[mi][3] = Q2[(r0+8)*9 + t + 4];
        }
        #pragma unroll
        for (int ni = 0; ni < 3; ni++) {
            int r0 = nw*24 + ni*8 + g;
            bf[ni][0] = K2[r0*9 + t];
            bf[ni][1] = K2[r0*9 + t + 4];
        }
        #pragma unroll
        for (int mi = 0; mi < 3; mi++)
            #pragma unroll
            for (int ni = 0; ni < 3; ni++) {
                asm volatile(
                    "mma.sync.aligned.m16n8k16.row.col.f32.f16.f16.f32 "
                    "{%0,%1,%2,%3}, {%4,%5,%6,%7}, {%8,%9}, {%0,%1,%2,%3};"
                    : "+f"(acc[mi][ni][0]), "+f"(acc[mi][ni][1]),
                      "+f"(acc[mi][ni][2]), "+f"(acc[mi][ni][3])
                    : "r"(af[mi][0]), "r"(af[mi][1]), "r"(af[mi][2]), "r"(af[mi][3]),
                      "r"(bf[ni][0]), "r"(bf[ni][1]));
            }

        // store prefetched data into the other buffer
        if (more) {
            #pragma unroll
            for (int r = 0; r < 3; r++) {
                __half2 hq = *(__half2*)&pq[r];
                __half2 hk = *(__half2*)&pk[r];
                Qs[cur^1][(2*sci2[r])*18 + skk[r]]   = __low2half(hq);
                Qs[cur^1][(2*sci2[r]+1)*18 + skk[r]] = __high2half(hq);
                Ks[cur^1][(2*sci2[r])*18 + skk[r]]   = __low2half(hk);
                Ks[cur^1][(2*sci2[r]+1)*18 + skk[r]] = __high2half(hk);
            }
        }
        __syncthreads();
    }

    // ---- writeback: D[cq][ck] -> attn4[(ks*768 + b*96 + ck)*864 + cq*9 + p]
    #pragma unroll
    for (int mi = 0; mi < 3; mi++) {
        #pragma unroll
        for (int ni = 0; ni < 3; ni++) {
            int cq0 = mw*48 + mi*16 + g;
            int ck0 = nw*24 + ni*8 + 2*t;
            float a0 = acc[mi][ni][0], a1 = acc[mi][ni][1];
            float a2 = acc[mi][ni][2], a3 = acc[mi][ni][3];
            size_t rbase = (size_t)(ks*768 + b*CCH);
            attn4[(rbase + ck0    )*864 + cq0*9 + p]     = a0;
            attn4[(rbase + ck0 + 1)*864 + cq0*9 + p]     = a1;
            attn4[(rbase + ck0    )*864 + (cq0+8)*9 + p] = a2;
            attn4[(rbase + ck0 + 1)*864 + (cq0+8)*9 + p] = a3;
        }
    }
}

// ---------------- softmax + direct fragment-layout weight emit -------------
__global__ __launch_bounds__(256)
void softmax_kernel(const float* __restrict__ attn4, unsigned* __restrict__ wath)
{
    const int rowid = blockIdx.x;
    const float scale = 0.034020690871988585f;   // 1/sqrt(864)
    const int tid = threadIdx.x;
    __shared__ float red[256];
    __shared__ float sm[864];

    float v[4];
    float mx = -1e30f;
    #pragma unroll
    for (int it=0; it<4; it++) {
        int idx = tid + it*256;
        float s = -1e30f;
        if (idx < 864) {
            s = 0.f;
            #pragma unroll
            for (int ks = 0; ks < NSPLIT; ks++)
                s += attn4[((size_t)(ks*768 + rowid))*864 + idx];
            s *= scale;
        }
        v[it] = s;
        mx = fmaxf(mx, s);
    }
    red[tid] = mx; __syncthreads();
    for (int s=128; s>0; s>>=1) { if (tid<s) red[tid]=fmaxf(red[tid],red[tid+s]); __syncthreads(); }
    mx = red[0]; __syncthreads();

    float sum = 0.f;
    #pragma unroll
    for (int it=0; it<4; it++) {
        int idx = tid + it*256;
        v[it] = (idx < 864) ? expf(v[it]-mx) : 0.f;
        sum += v[it];
    }
    red[tid] = sum; __syncthreads();
    for (int s=128; s>0; s>>=1) { if (tid<s) red[tid]+=red[tid+s]; __syncthreads(); }
    float inv = 1.f/red[0];
    __syncthreads();

    #pragma unroll
    for (int it=0; it<4; it++) {
        int idx = tid + it*256;
        if (idx < 864) sm[idx] = v[it]*inv;
    }
    __syncthreads();

    const int bb = rowid / CCH, ck = rowid - (rowid/CCH)*CCH;
    const int mt = ck >> 4, gq = ck & 7, hiw = (ck >> 3) & 1;
    #pragma unroll
    for (int it = 0; it < 2; it++) {
        int e = tid + it*256;
        if (e < 432) {
            int u = e / 9, tap = e - 9*u;
            int chunk = u >> 3, hi2 = (u & 7) >> 2, t = u & 3;
            int w = hiw | (hi2 << 1);
            int lane = (gq << 2) | t;
            wath[(size_t)bb*6*WCH2 + chunk*WCH2 + ((tap*6 + mt)*32 + lane)*4 + w] =
                packh2(sm[2*u*9 + tap], sm[(2*u + 1)*9 + tap]);
        }
    }
}

// ---------------- BN finalize: sums -> mean/istd ----------------
__global__ void bnfinal_kernel()
{
    int e = threadIdx.x;
    if (e >= 3*CCH) return;
    const float invN = 1.f / (float)(BATCH*HW);
    float m = g_bnsum[e] * invN;
    float var = g_bnsq[e] * invN - m*m;
    g_mean[e] = m;
    g_istd[e] = rsqrtf(var + 1e-5f);
}

// ---------------- final fuse (vectorized float4) ----------------
__global__ __launch_bounds__(256)
void finalize_kernel(const float* __restrict__ x1, const float* __restrict__ x2,
                     const float* __restrict__ y1, const float* __restrict__ y2,
                     const float* __restrict__ y3,
                     float* __restrict__ out, int writeSecond)
{
    const int hw = blockIdx.x*1024 + threadIdx.x*4;
    const int c  = blockIdx.y;
    const int b  = blockIdx.z;
    size_t oidx = ((size_t)b*2*CCH + c)*HW + hw;
    float4 xv, yv;
    if (c < CCH) {
        size_t off = ((size_t)b*CCH + c)*HW + hw;
        xv = *(const float4*)&x1[off];
        float4 a = *(const float4*)&y1[off];
        float4 g4 = *(const float4*)&y2[off];
        float m1 = g_mean[c],       s1 = g_istd[c];
        float m2 = g_mean[CCH+c],   s2 = g_istd[CCH+c];
        yv.x = ((a.x-m1)*s1)*((g4.x-m2)*s2);
        yv.y = ((a.y-m1)*s1)*((g4.y-m2)*s2);
        yv.z = ((a.z-m1)*s1)*((g4.z-m2)*s2);
        yv.w = ((a.w-m1)*s1)*((g4.w-m2)*s2);
    } else {
        int cc = c - CCH;
        size_t off = ((size_t)b*CCH + cc)*HW + hw;
        xv = *(const float4*)&x2[off];
        float4 a = *(const float4*)&y3[off];
        float m3 = g_mean[2*CCH+cc], s3 = g_istd[2*CCH+cc];
        yv.x = (a.x-m3)*s3; yv.y = (a.y-m3)*s3;
        yv.z = (a.z-m3)*s3; yv.w = (a.w-m3)*s3;
    }
    float4 o;
    o.x = xv.x + yv.x; o.y = xv.y + yv.y;
    o.z = xv.z + yv.z; o.w = xv.w + yv.w;
    *(float4*)&out[oidx] = o;
    if (writeSecond) *(float4*)&out[N1OUT + oidx] = xv;
}

// ---------------- launch ----------------
extern "C" void kernel_launch(void* const* d_in, const int* in_sizes, int n_in,
                              void* d_out, int out_size)
{
    const float* x1  = (const float*)d_in[0];
    const float* x2  = (const float*)d_in[1];
    const float* w1  = (const float*)d_in[2];
    const float* w2  = (const float*)d_in[3];
    const float* wa1 = (const float*)d_in[4];
    const float* wa2 = (const float*)d_in[5];
    const float* wa3 = (const float*)d_in[6];
    float* out = (float*)d_out;

    float *y1,*y2,*y3,*attn4;
    unsigned *x1h,*x2h,*qh,*kh,*vh,*w1h,*w2h,*wa1h,*wa2h,*wa3h,*wath;
    cudaGetSymbolAddress((void**)&y1,   g_y1);
    cudaGetSymbolAddress((void**)&y2,   g_y2);
    cudaGetSymbolAddress((void**)&y3,   g_y3);
    cudaGetSymbolAddress((void**)&attn4,g_attn4);
    cudaGetSymbolAddress((void**)&x1h,  g_x1h);
    cudaGetSymbolAddress((void**)&x2h,  g_x2h);
    cudaGetSymbolAddress((void**)&qh,   g_qh);
    cudaGetSymbolAddress((void**)&kh,   g_kh);
    cudaGetSymbolAddress((void**)&vh,   g_vh);
    cudaGetSymbolAddress((void**)&w1h,  g_w1h);
    cudaGetSymbolAddress((void**)&w2h,  g_w2h);
    cudaGetSymbolAddress((void**)&wa1h, g_wa1h);
    cudaGetSymbolAddress((void**)&wa2h, g_wa2h);
    cudaGetSymbolAddress((void**)&wa3h, g_wa3h);
    cudaGetSymbolAddress((void**)&wath, g_wath);

    static int smem_set = 0;
    const int CONV_SMEM = (2*WCH2 + 2*PBUF) * 4;   // 68096 B
    if (!smem_set) {
        cudaFuncSetAttribute(conv3x3_fp16_kernel,
                             cudaFuncAttributeMaxDynamicSharedMemorySize, CONV_SMEM);
        smem_set = 1;
    }

    // 1. inputs -> interleaved half2
    cvt_pair_kernel<<<dim3((NPIX2+255)/256, 2), 256>>>(x1, x1h, x2, x2h);

    // 2. weights -> fragment layout; zero BN stat buffers
    wprep_all_kernel<<<dim3((12*WCH2+255)/256, 5), 256>>>(
        w1, w2, wa1, wa2, wa3, w1h, w2h, wa1h, wa2h, wa3h);

    // 3. five convs in one launch; y1/y2 accumulate BN stats in epilogue
    {
        ConvJobs jb{};
        jb.j[0] = { x1h, x1h, w1h,  0, y1, 0,  0, 48, 48, 0 };
        jb.j[1] = { x2h, x2h, w2h,  0, y2, 0,  0, 48, 48, 1 };
        jb.j[2] = { x1h, x2h, wa1h, 0, 0,  qh, 1, 48, 96, -1 };
        jb.j[3] = { x1h, x2h, wa2h, 0, 0,  kh, 1, 48, 96, -1 };
        jb.j[4] = { x1h, x2h, wa3h, 0, 0,  vh, 1, 48, 96, -1 };
        conv3x3_fp16_kernel<<<dim3(72, 5, 8), 192, CONV_SMEM>>>(jb);
    }

    // 4. attention logits (tensor cores) + softmax -> y3-conv weights
    attn_mma_kernel<<<dim3(9, 8, NSPLIT), 256>>>(qh, kh, attn4);
    softmax_kernel<<<BATCH*CCH, 256>>>(attn4, wath);

    // 5. attn @ v_unf == per-batch conv; y3 stats fused
    {
        ConvJobs jb{};
        jb.j[0] = { vh, vh, wath, 6L*WCH2, y3, 0, 0, 48, 48, 2 };
        conv3x3_fp16_kernel<<<dim3(72, 1, 8), 192, CONV_SMEM>>>(jb);
    }

    // 6. BN mean/istd + fused epilogue
    bnfinal_kernel<<<1, 3*CCH>>>();
    int writeSecond = (out_size >= 2*N1OUT) ? 1 : 0;
    finalize_kernel<<<dim3(9, 2*CCH, BATCH), 256>>>(x1, x2, y1, y2, y3, out, writeSecond);
}

// round 17
// speedup vs baseline: 1.2731x; 1.0089x over previous
#include <cuda_runtime.h>
#include <cuda_fp16.h>
#include <math.h>

#define BATCH 8
#define CCH 96
#define HH 96
#define WW 96
#define HW (HH*WW)                 // 9216
#define NPIX 7077888               // 8*96*96*96
#define NPIX2 (NPIX/2)
#define N1OUT 14155776             // 8*192*96*96
#define NSPLIT 4

#define WCH2  6912
#define PRS2  40
#define PCIS  400
#define PBUF  1600

// ---------------- scratch ----------------
__device__ float g_y1[NPIX];
__device__ float g_y2[NPIX];
__device__ float g_y3[NPIX];
__device__ float g_attn4[NSPLIT*BATCH*CCH*CCH*9];
__device__ float g_mean[3*CCH];
__device__ float g_istd[3*CCH];
__device__ float g_bnsum[3*CCH];
__device__ float g_bnsq [3*CCH];

__device__ __align__(16) unsigned g_x1h[NPIX2];
__device__ __align__(16) unsigned g_x2h[NPIX2];
__device__ __align__(16) unsigned g_qh [NPIX2];
__device__ __align__(16) unsigned g_kh [NPIX2];
__device__ __align__(16) unsigned g_vh [NPIX2];
__device__ __align__(16) unsigned g_w1h [6*WCH2];
__device__ __align__(16) unsigned g_w2h [6*WCH2];
__device__ __align__(16) unsigned g_wa1h[12*WCH2];
__device__ __align__(16) unsigned g_wa2h[12*WCH2];
__device__ __align__(16) unsigned g_wa3h[12*WCH2];
__device__ __align__(16) unsigned g_wath[BATCH*6*WCH2];

struct ConvJob {
    const unsigned* inA;
    const unsigned* inB;
    const unsigned* wh;
    long  wstride;
    float* outf;
    unsigned* outh;
    int outmode;      // 0=NCHW fp32, 1=interleaved half2
    int csplit2;
    int cin2;
    int statIdx;      // -1 = none; else BN stats row (0..2)
};
struct ConvJobs {
    ConvJob j[3];
};

__device__ __forceinline__ unsigned packh2(float a, float b) {
    __half2 h = __floats2half2_rn(a, b);
    return *(unsigned*)&h;
}

// ---------------- fp32 -> ci-pair-interleaved half2 ----------------
__global__ __launch_bounds__(256)
void cvt_pair_kernel(const float* __restrict__ s1, unsigned* __restrict__ d1,
                     const float* __restrict__ s2, unsigned* __restrict__ d2)
{
    const float* src = blockIdx.y ? s2 : s1;
    unsigned* dst    = blockIdx.y ? d2 : d1;
    int e = blockIdx.x*256 + threadIdx.x;
    if (e >= NPIX2) return;
    int b = e / (48*HW), r = e - b*48*HW;
    int ci2 = r / HW, hw = r - ci2*HW;
    size_t off = ((size_t)b*CCH + 2*ci2)*HW + hw;
    dst[e] = packh2(src[off], src[off + HW]);
}

// ---------------- weight pre-transform (+ zero BN stat buffers) ------------
__global__ __launch_bounds__(256)
void wprep_all_kernel(const float* __restrict__ w1, const float* __restrict__ w2,
                      const float* __restrict__ wa1, const float* __restrict__ wa2,
                      const float* __restrict__ wa3,
                      unsigned* __restrict__ d1, unsigned* __restrict__ d2,
                      unsigned* __restrict__ d3, unsigned* __restrict__ d4,
                      unsigned* __restrict__ d5)
{
    const int id = blockIdx.y;
    if (id == 0) {
        int z = blockIdx.x*256 + threadIdx.x;
        if (z < 3*CCH) { g_bnsum[z] = 0.f; g_bnsq[z] = 0.f; }
    }
    const float* src; unsigned* dst; int cin;
    if      (id == 0) { src = w1;  dst = d1; cin = 96;  }
    else if (id == 1) { src = w2;  dst = d2; cin = 96;  }
    else if (id == 2) { src = wa1; dst = d3; cin = 192; }
    else if (id == 3) { src = wa2; dst = d4; cin = 192; }
    else              { src = wa3; dst = d5; cin = 192; }
    const int nwords = (cin >> 4) * WCH2;
    int e = blockIdx.x*256 + threadIdx.x;
    if (e >= nwords) return;
    int chunk = e / WCH2, rm = e - chunk*WCH2;
    int w = rm & 3, lane = (rm >> 2) & 31, mtap = rm >> 7;
    int tap = mtap / 6, mt = mtap - 6*tap;
    int g = lane >> 2, t = lane & 3;
    int co = mt*16 + g + (w & 1)*8;
    int ci = chunk*16 + 2*t + ((w >> 1) & 1)*8;
    dst[e] = packh2(src[((size_t)co*cin + ci)*9 + tap],
                    src[((size_t)co*cin + ci + 1)*9 + tap]);
}

// ---------------- tensor-core 3x3 conv, fp16 m16n8k16, multi-job -----------
__global__ __launch_bounds__(192, 2)
void conv3x3_fp16_kernel(ConvJobs jobs)
{
    extern __shared__ unsigned dsm[];
    const ConvJob J = jobs.j[blockIdx.y];
    const unsigned* __restrict__ inAh = J.inA;
    const unsigned* __restrict__ inBh = J.inB;
    const int csplit2 = J.csplit2, cin2 = J.cin2;

    const int tid  = threadIdx.x;
    const int lane = tid & 31, wid = tid >> 5;
    const int g = lane >> 2, t = lane & 3;
    const int cog = wid >> 1;
    const int rp  = wid & 1;
    const int b   = blockIdx.z;
    const int byk = blockIdx.x / 6, bxk = blockIdx.x - 6*byk;
    const int by0 = byk*8, bx0 = bxk*16;

    const unsigned smem_b = (unsigned)__cvta_generic_to_shared(dsm);
    unsigned* psmem = dsm + 2*WCH2;

    int pgoff[8], psoff[8], pci[8];
    bool lok[8], sok[8];
    #pragma unroll
    for (int it = 0; it < 8; it++) {
        int e = tid + it*192;
        int ci = e / 180, r2 = e - ci*180;
        int row = r2 / 18, col = r2 - row*18;
        int gh = by0 + row - 1, gw = bx0 + col - 1;
        bool inp = (e < 1440);
        bool ok = inp && gh >= 0 && gh < HH && gw >= 0 && gw < WW;
        lok[it] = ok; sok[it] = inp;
        pgoff[it] = ok ? gh*WW + gw : 0;
        psoff[it] = inp ? (ci & 3)*PCIS + row*PRS2 + col*2 + (ci >> 2) : 0;
        pci[it]   = ci;
    }

    const unsigned* wsrc0 = J.wh + (size_t)J.wstride*b;

    #pragma unroll
    for (int k2 = 0; k2 < 9; k2++) {
        int idx = tid + k2*192;
        asm volatile("cp.async.cg.shared.global [%0], [%1], 16;"
                     :: "r"(smem_b + idx*16), "l"(wsrc0 + idx*4) : "memory");
    }
    asm volatile("cp.async.commit_group;" ::: "memory");
    {
        unsigned pv[8];
        #pragma unroll
        for (int it = 0; it < 8; it++) {
            int gci = pci[it];
            const unsigned* src = (gci < csplit2)
                ? inAh + ((size_t)b*csplit2 + gci)*HW
                : inBh + ((size_t)b*(cin2-csplit2) + (gci-csplit2))*HW;
            pv[it] = lok[it] ? src[pgoff[it]] : 0u;
        }
        #pragma unroll
        for (int it = 0; it < 8; it++)
            if (sok[it]) psmem[psoff[it]] = pv[it];
    }
    asm volatile("cp.async.wait_group 0;" ::: "memory");
    __syncthreads();

    float acc[2][8][4];
    #pragma unroll
    for (int m=0;m<2;m++)
        #pragma unroll
        for (int nt=0;nt<8;nt++)
            #pragma unroll
            for (int r=0;r<4;r++) acc[m][nt][r] = 0.f;

    const int nchunk = cin2 >> 3;
    for (int ch = 0; ch < nchunk; ch++) {
        const int cur = ch & 1;
        const bool more = (ch + 1 < nchunk);

        unsigned pv[8];
        if (more) {
            const unsigned* wsrc = wsrc0 + (size_t)(ch+1)*WCH2;
            const unsigned wdst = smem_b + (cur^1)*WCH2*4;
            #pragma unroll
            for (int k2 = 0; k2 < 9; k2++) {
                int idx = tid + k2*192;
                asm volatile("cp.async.cg.shared.global [%0], [%1], 16;"
                             :: "r"(wdst + idx*16), "l"(wsrc + idx*4) : "memory");
            }
            asm volatile("cp.async.commit_group;" ::: "memory");
            const int ci0 = (ch+1) << 3;
            #pragma unroll
            for (int it = 0; it < 8; it++) {
                int gci = ci0 + pci[it];
                const unsigned* src = (gci < csplit2)
                    ? inAh + ((size_t)b*csplit2 + gci)*HW
                    : inBh + ((size_t)b*(cin2-csplit2) + (gci-csplit2))*HW;
                pv[it] = lok[it] ? src[pgoff[it]] : 0u;
            }
        }

        const unsigned wbase = smem_b + cur*WCH2*4;
        const unsigned pbase = smem_b + (2*WCH2 + cur*PBUF)*4;
        #pragma unroll
        for (int tap = 0; tap < 9; tap++) {
            const int i = tap/3, j = tap - 3*(tap/3);
            unsigned a[2][4];
            #pragma unroll
            for (int m = 0; m < 2; m++) {
                const int mt = cog*2 + m;
                asm volatile("ld.shared.v4.b32 {%0,%1,%2,%3}, [%4];"
                    : "=r"(a[m][0]), "=r"(a[m][1]), "=r"(a[m][2]), "=r"(a[m][3])
                    : "r"(wbase + (((tap*6 + mt)*32 + lane)*16)));
            }
            #pragma unroll
            for (int nt = 0; nt < 8; nt++) {
                const int py = 4*rp + (nt & 3);
                const int cb2 = (nt >> 2) * 8;
                unsigned b0, b1;
                asm volatile("ld.shared.v2.b32 {%0,%1}, [%2];"
                    : "=r"(b0), "=r"(b1)
                    : "r"(pbase + (t*PCIS + (py+i)*PRS2 + (cb2+j+g)*2)*4));
                #pragma unroll
                for (int m = 0; m < 2; m++) {
                    asm volatile(
                        "mma.sync.aligned.m16n8k16.row.col.f32.f16.f16.f32 "
                        "{%0,%1,%2,%3}, {%4,%5,%6,%7}, {%8,%9}, {%0,%1,%2,%3};"
                        : "+f"(acc[m][nt][0]), "+f"(acc[m][nt][1]),
                          "+f"(acc[m][nt][2]), "+f"(acc[m][nt][3])
                        : "r"(a[m][0]), "r"(a[m][1]), "r"(a[m][2]), "r"(a[m][3]),
                          "r"(b0), "r"(b1));
                }
            }
        }

        if (more) {
            unsigned* pd = psmem + (cur^1)*PBUF;
            #pragma unroll
            for (int it = 0; it < 8; it++)
                if (sok[it]) pd[psoff[it]] = pv[it];
            asm volatile("cp.async.wait_group 0;" ::: "memory");
        }
        __syncthreads();
    }

    // ---- writeback ----
    if (J.outmode == 0) {
        float* out = J.outf;
        #pragma unroll
        for (int m = 0; m < 2; m++)
            #pragma unroll
            for (int nt = 0; nt < 8; nt++) {
                int co  = cog*32 + m*16 + g;
                int row = by0 + 4*rp + (nt & 3);
                int col = bx0 + (nt >> 2)*8 + 2*t;
                size_t base = (((size_t)b*CCH + co)*HH + row)*WW + col;
                *(float2*)&out[base]        = make_float2(acc[m][nt][0], acc[m][nt][1]);
                *(float2*)&out[base + 8*HW] = make_float2(acc[m][nt][2], acc[m][nt][3]);
            }
        if (J.statIdx >= 0) {
            #pragma unroll
            for (int m = 0; m < 2; m++) {
                float s0=0.f, q0=0.f, s1=0.f, q1=0.f;
                #pragma unroll
                for (int nt = 0; nt < 8; nt++) {
                    float a0 = acc[m][nt][0], a1 = acc[m][nt][1];
                    float a2 = acc[m][nt][2], a3 = acc[m][nt][3];
                    s0 += a0 + a1;  q0 = fmaf(a0,a0,fmaf(a1,a1,q0));
                    s1 += a2 + a3;  q1 = fmaf(a2,a2,fmaf(a3,a3,q1));
                }
                s0 += __shfl_xor_sync(0xFFFFFFFFu, s0, 1);
                s0 += __shfl_xor_sync(0xFFFFFFFFu, s0, 2);
                q0 += __shfl_xor_sync(0xFFFFFFFFu, q0, 1);
                q0 += __shfl_xor_sync(0xFFFFFFFFu, q0, 2);
                s1 += __shfl_xor_sync(0xFFFFFFFFu, s1, 1);
                s1 += __shfl_xor_sync(0xFFFFFFFFu, s1, 2);
                q1 += __shfl_xor_sync(0xFFFFFFFFu, q1, 1);
                q1 += __shfl_xor_sync(0xFFFFFFFFu, q1, 2);
                if (t == 0) {
                    int co = cog*32 + m*16 + g;
                    atomicAdd(&g_bnsum[J.statIdx*CCH + co],     s0);
                    atomicAdd(&g_bnsq [J.statIdx*CCH + co],     q0);
                    atomicAdd(&g_bnsum[J.statIdx*CCH + co + 8], s1);
                    atomicAdd(&g_bnsq [J.statIdx*CCH + co + 8], q1);
                }
            }
        }
    } else {
        unsigned* outh = J.outh;
        #pragma unroll
        for (int m = 0; m < 2; m++)
            #pragma unroll
            for (int nt = 0; nt < 8; nt++) {
                float a0 = acc[m][nt][0], a1 = acc[m][nt][1];
                float a2 = acc[m][nt][2], a3 = acc[m][nt][3];
                float p0 = __shfl_xor_sync(0xFFFFFFFFu, a0, 4);
                float p1 = __shfl_xor_sync(0xFFFFFFFFu, a1, 4);
                float p2 = __shfl_xor_sync(0xFFFFFFFFu, a2, 4);
                float p3 = __shfl_xor_sync(0xFFFFFFFFu, a3, 4);
                int row = by0 + 4*rp + (nt & 3);
                int col = bx0 + (nt >> 2)*8 + 2*t;
                int B = cog*32 + m*16;
                int ci2; unsigned w0, w1;
                if ((g & 1) == 0) {
                    ci2 = (B >> 1) + (g >> 1);
                    w0 = packh2(a0, p0); w1 = packh2(a1, p1);
                } else {
                    ci2 = (B >> 1) + 4 + ((g - 1) >> 1);
                    w0 = packh2(p2, a2); w1 = packh2(p3, a3);
                }
                *(uint2*)&outh[((size_t)b*48 + ci2)*HW + row*WW + col] =
                    make_uint2(w0, w1);
            }
    }
}

// ---------------- attention logits on tensor cores ----------------
__global__ __launch_bounds__(256)
void attn_mma_kernel(const unsigned* __restrict__ qh, const unsigned* __restrict__ kh,
                     float* __restrict__ attn4)
{
    const int p = blockIdx.x;
    const int b = blockIdx.y;
    const int ks = blockIdx.z;
    const int i = p/3, j = p - 3*(p/3);
    const int tid = threadIdx.x;
    const int lane = tid & 31, wid = tid >> 5;
    const int g = lane >> 2, t = lane & 3;
    const int mw = wid >> 2, nw = wid & 3;

    __shared__ __half Qs[2][96*18];
    __shared__ __half Ks[2][96*18];

    float acc[3][3][4];
    #pragma unroll
    for (int mi=0;mi<3;mi++)
        #pragma unroll
        for (int ni=0;ni<3;ni++)
            #pragma unroll
            for (int r=0;r<4;r++) acc[mi][ni][r] = 0.f;

    int sci2[3], skk[3];
    #pragma unroll
    for (int r = 0; r < 3; r++) { int e = tid + r*256; sci2[r] = e >> 4; skk[r] = e & 15; }

    const unsigned* qb = qh + (size_t)b*48*HW;
    const unsigned* kb = kh + (size_t)b*48*HW;
    const int l0 = ks*256;

    {
        unsigned pq[3], pk[3];
        #pragma unroll
        for (int r = 0; r < 3; r++) {
            int l = l0 + skk[r];
            int a = (3*(l>>5) + i)*WW + 3*(l&31) + j;
            pq[r] = qb[(size_t)sci2[r]*HW + a];
            pk[r] = kb[(size_t)sci2[r]*HW + a];
        }
        #pragma unroll
        for (int r = 0; r < 3; r++) {
            __half2 hq = *(__half2*)&pq[r];
            __half2 hk = *(__half2*)&pk[r];
            Qs[0][(2*sci2[r])*18 + skk[r]]     = __low2half(hq);
            Qs[0][(2*sci2[r]+1)*18 + skk[r]]   = __high2half(hq);
            Ks[0][(2*sci2[r])*18 + skk[r]]     = __low2half(hk);
            Ks[0][(2*sci2[r]+1)*18 + skk[r]]   = __high2half(hk);
        }
    }
    __syncthreads();

    for (int step = 0; step < 16; step++) {
        const int cur = step & 1;
        const bool more = (step < 15);

        unsigned pq[3], pk[3];
        if (more) {
            int lb = l0 + (step+1)*16;
            #pragma unroll
            for (int r = 0; r < 3; r++) {
                int l = lb + skk[r];
                int a = (3*(l>>5) + i)*WW + 3*(l&31) + j;
                pq[r] = qb[(size_t)sci2[r]*HW + a];
                pk[r] = kb[(size_t)sci2[r]*HW + a];
            }
        }

        const unsigned* Q2 = (const unsigned*)Qs[cur];
        const unsigned* K2 = (const unsigned*)Ks[cur];
        unsigned af[3][4], bf[3][2];
        #pragma unroll
        for (int mi = 0; mi < 3; mi++) {
            int r0 = mw*48 + mi*16 + g;
            af[mi][0] = Q2[r0*9 + t];
            af[mi][1] = Q2[(r0+8)*9 + t];
            af[mi][2] = Q2[r0*9 + t + 4];
            af[mi][3] = Q2[(r0+8)*9 + t + 4];
        }
        #pragma unroll
        for (int ni = 0; ni < 3; ni++) {
            int r0 = nw*24 + ni*8 + g;
            bf[ni][0] = K2[r0*9 + t];
            bf[ni][1] = K2[r0*9 + t + 4];
        }
        #pragma unroll
        for (int mi = 0; mi < 3; mi++)
            #pragma unroll
            for (int ni = 0; ni < 3; ni++) {
                asm volatile(
                    "mma.sync.aligned.m16n8k16.row.col.f32.f16.f16.f32 "
                    "{%0,%1,%2,%3}, {%4,%5,%6,%7}, {%8,%9}, {%0,%1,%2,%3};"
                    : "+f"(acc[mi][ni][0]), "+f"(acc[mi][ni][1]),
                      "+f"(acc[mi][ni][2]), "+f"(acc[mi][ni][3])
                    : "r"(af[mi][0]), "r"(af[mi][1]), "r"(af[mi][2]), "r"(af[mi][3]),
                      "r"(bf[ni][0]), "r"(bf[ni][1]));
            }

        if (more) {
            #pragma unroll
            for (int r = 0; r < 3; r++) {
                __half2 hq = *(__half2*)&pq[r];
                __half2 hk = *(__half2*)&pk[r];
                Qs[cur^1][(2*sci2[r])*18 + skk[r]]   = __low2half(hq);
                Qs[cur^1][(2*sci2[r]+1)*18 + skk[r]] = __high2half(hq);
                Ks[cur^1][(2*sci2[r])*18 + skk[r]]   = __low2half(hk);
                Ks[cur^1][(2*sci2[r]+1)*18 + skk[r]] = __high2half(hk);
            }
        }
        __syncthreads();
    }

    #pragma unroll
    for (int mi = 0; mi < 3; mi++) {
        #pragma unroll
        for (int ni = 0; ni < 3; ni++) {
            int cq0 = mw*48 + mi*16 + g;
            int ck0 = nw*24 + ni*8 + 2*t;
            float a0 = acc[mi][ni][0], a1 = acc[mi][ni][1];
            float a2 = acc[mi][ni][2], a3 = acc[mi][ni][3];
            size_t rbase = (size_t)(ks*768 + b*CCH);
            attn4[(rbase + ck0    )*864 + cq0*9 + p]     = a0;
            attn4[(rbase + ck0 + 1)*864 + cq0*9 + p]     = a1;
            attn4[(rbase + ck0    )*864 + (cq0+8)*9 + p] = a2;
            attn4[(rbase + ck0 + 1)*864 + (cq0+8)*9 + p] = a3;
        }
    }
}

// ---------------- softmax + direct fragment-layout weight emit -------------
__global__ __launch_bounds__(256)
void softmax_kernel(const float* __restrict__ attn4, unsigned* __restrict__ wath)
{
    const int rowid = blockIdx.x;
    const float scale = 0.034020690871988585f;   // 1/sqrt(864)
    const int tid = threadIdx.x;
    __shared__ float red[256];
    __shared__ float sm[864];

    float v[4];
    float mx = -1e30f;
    #pragma unroll
    for (int it=0; it<4; it++) {
        int idx = tid + it*256;
        float s = -1e30f;
        if (idx < 864) {
            s = 0.f;
            #pragma unroll
            for (int ks = 0; ks < NSPLIT; ks++)
                s += attn4[((size_t)(ks*768 + rowid))*864 + idx];
            s *= scale;
        }
        v[it] = s;
        mx = fmaxf(mx, s);
    }
    red[tid] = mx; __syncthreads();
    for (int s=128; s>0; s>>=1) { if (tid<s) red[tid]=fmaxf(red[tid],red[tid+s]); __syncthreads(); }
    mx = red[0]; __syncthreads();

    float sum = 0.f;
    #pragma unroll
    for (int it=0; it<4; it++) {
        int idx = tid + it*256;
        v[it] = (idx < 864) ? expf(v[it]-mx) : 0.f;
        sum += v[it];
    }
    red[tid] = sum; __syncthreads();
    for (int s=128; s>0; s>>=1) { if (tid<s) red[tid]+=red[tid+s]; __syncthreads(); }
    float inv = 1.f/red[0];
    __syncthreads();

    #pragma unroll
    for (int it=0; it<4; it++) {
        int idx = tid + it*256;
        if (idx < 864) sm[idx] = v[it]*inv;
    }
    __syncthreads();

    const int bb = rowid / CCH, ck = rowid - (rowid/CCH)*CCH;
    const int mt = ck >> 4, gq = ck & 7, hiw = (ck >> 3) & 1;
    #pragma unroll
    for (int it = 0; it < 2; it++) {
        int e = tid + it*256;
        if (e < 432) {
            int u = e / 9, tap = e - 9*u;
            int chunk = u >> 3, hi2 = (u & 7) >> 2, t = u & 3;
            int w = hiw | (hi2 << 1);
            int lane = (gq << 2) | t;
            wath[(size_t)bb*6*WCH2 + chunk*WCH2 + ((tap*6 + mt)*32 + lane)*4 + w] =
                packh2(sm[2*u*9 + tap], sm[(2*u + 1)*9 + tap]);
        }
    }
}

// ---------------- BN finalize: sums -> mean/istd ----------------
__global__ void bnfinal_kernel()
{
    int e = threadIdx.x;
    if (e >= 3*CCH) return;
    const float invN = 1.f / (float)(BATCH*HW);
    float m = g_bnsum[e] * invN;
    float var = g_bnsq[e] * invN - m*m;
    g_mean[e] = m;
    g_istd[e] = rsqrtf(var + 1e-5f);
}

// ---------------- final fuse (vectorized float4) ----------------
__global__ __launch_bounds__(256)
void finalize_kernel(const float* __restrict__ x1, const float* __restrict__ x2,
                     const float* __restrict__ y1, const float* __restrict__ y2,
                     const float* __restrict__ y3,
                     float* __restrict__ out, int writeSecond)
{
    const int hw = blockIdx.x*1024 + threadIdx.x*4;
    const int c  = blockIdx.y;
    const int b  = blockIdx.z;
    size_t oidx = ((size_t)b*2*CCH + c)*HW + hw;
    float4 xv, yv;
    if (c < CCH) {
        size_t off = ((size_t)b*CCH + c)*HW + hw;
        xv = *(const float4*)&x1[off];
        float4 a = *(const float4*)&y1[off];
        float4 g4 = *(const float4*)&y2[off];
        float m1 = g_mean[c],       s1 = g_istd[c];
        float m2 = g_mean[CCH+c],   s2 = g_istd[CCH+c];
        yv.x = ((a.x-m1)*s1)*((g4.x-m2)*s2);
        yv.y = ((a.y-m1)*s1)*((g4.y-m2)*s2);
        yv.z = ((a.z-m1)*s1)*((g4.z-m2)*s2);
        yv.w = ((a.w-m1)*s1)*((g4.w-m2)*s2);
    } else {
        int cc = c - CCH;
        size_t off = ((size_t)b*CCH + cc)*HW + hw;
        xv = *(const float4*)&x2[off];
        float4 a = *(const float4*)&y3[off];
        float m3 = g_mean[2*CCH+cc], s3 = g_istd[2*CCH+cc];
        yv.x = (a.x-m3)*s3; yv.y = (a.y-m3)*s3;
        yv.z = (a.z-m3)*s3; yv.w = (a.w-m3)*s3;
    }
    float4 o;
    o.x = xv.x + yv.x; o.y = xv.y + yv.y;
    o.z = xv.z + yv.z; o.w = xv.w + yv.w;
    *(float4*)&out[oidx] = o;
    if (writeSecond) *(float4*)&out[N1OUT + oidx] = xv;
}

// ---------------- launch ----------------
extern "C" void kernel_launch(void* const* d_in, const int* in_sizes, int n_in,
                              void* d_out, int out_size)
{
    const float* x1  = (const float*)d_in[0];
    const float* x2  = (const float*)d_in[1];
    const float* w1  = (const float*)d_in[2];
    const float* w2  = (const float*)d_in[3];
    const float* wa1 = (const float*)d_in[4];
    const float* wa2 = (const float*)d_in[5];
    const float* wa3 = (const float*)d_in[6];
    float* out = (float*)d_out;

    float *y1,*y2,*y3,*attn4;
    unsigned *x1h,*x2h,*qh,*kh,*vh,*w1h,*w2h,*wa1h,*wa2h,*wa3h,*wath;
    cudaGetSymbolAddress((void**)&y1,   g_y1);
    cudaGetSymbolAddress((void**)&y2,   g_y2);
    cudaGetSymbolAddress((void**)&y3,   g_y3);
    cudaGetSymbolAddress((void**)&attn4,g_attn4);
    cudaGetSymbolAddress((void**)&x1h,  g_x1h);
    cudaGetSymbolAddress((void**)&x2h,  g_x2h);
    cudaGetSymbolAddress((void**)&qh,   g_qh);
    cudaGetSymbolAddress((void**)&kh,   g_kh);
    cudaGetSymbolAddress((void**)&vh,   g_vh);
    cudaGetSymbolAddress((void**)&w1h,  g_w1h);
    cudaGetSymbolAddress((void**)&w2h,  g_w2h);
    cudaGetSymbolAddress((void**)&wa1h, g_wa1h);
    cudaGetSymbolAddress((void**)&wa2h, g_wa2h);
    cudaGetSymbolAddress((void**)&wa3h, g_wa3h);
    cudaGetSymbolAddress((void**)&wath, g_wath);

    static int init_done = 0;
    static cudaStream_t s2;
    static cudaEvent_t evA, evB;
    const int CONV_SMEM = (2*WCH2 + 2*PBUF) * 4;   // 68096 B
    if (!init_done) {
        cudaFuncSetAttribute(conv3x3_fp16_kernel,
                             cudaFuncAttributeMaxDynamicSharedMemorySize, CONV_SMEM);
        cudaStreamCreateWithFlags(&s2, cudaStreamNonBlocking);
        cudaEventCreateWithFlags(&evA, cudaEventDisableTiming);
        cudaEventCreateWithFlags(&evB, cudaEventDisableTiming);
        init_done = 1;
    }

    // 1. inputs -> interleaved half2 ; weights -> fragment layout (+stat zero)
    cvt_pair_kernel<<<dim3((NPIX2+255)/256, 2), 256>>>(x1, x1h, x2, x2h);
    wprep_all_kernel<<<dim3((12*WCH2+255)/256, 5), 256>>>(
        w1, w2, wa1, wa2, wa3, w1h, w2h, wa1h, wa2h, wa3h);

    // 2. q,k,v convs first (the attn path's only dependency)
    {
        ConvJobs jb{};
        jb.j[0] = { x1h, x2h, wa1h, 0, 0, qh, 1, 48, 96, -1 };
        jb.j[1] = { x1h, x2h, wa2h, 0, 0, kh, 1, 48, 96, -1 };
        jb.j[2] = { x1h, x2h, wa3h, 0, 0, vh, 1, 48, 96, -1 };
        conv3x3_fp16_kernel<<<dim3(72, 3, 8), 192, CONV_SMEM>>>(jb);
    }
    cudaEventRecord(evA, 0);

    // 3a. fork: attn logits + softmax on side stream
    cudaStreamWaitEvent(s2, evA, 0);
    attn_mma_kernel<<<dim3(9, 8, NSPLIT), 256, 0, s2>>>(qh, kh, attn4);
    softmax_kernel<<<BATCH*CCH, 256, 0, s2>>>(attn4, wath);
    cudaEventRecord(evB, s2);

    // 3b. main stream concurrently: y1/y2 convs (+ BN stats)
    {
        ConvJobs jb{};
        jb.j[0] = { x1h, x1h, w1h, 0, y1, 0, 0, 48, 48, 0 };
        jb.j[1] = { x2h, x2h, w2h, 0, y2, 0, 0, 48, 48, 1 };
        conv3x3_fp16_kernel<<<dim3(72, 2, 8), 192, CONV_SMEM>>>(jb);
    }

    // 4. join, then attn @ v_unf == per-batch conv (+ y3 stats)
    cudaStreamWaitEvent(0, evB, 0);
    {
        ConvJobs jb{};
        jb.j[0] = { vh, vh, wath, 6L*WCH2, y3, 0, 0, 48, 48, 2 };
        conv3x3_fp16_kernel<<<dim3(72, 1, 8), 192, CONV_SMEM>>>(jb);
    }

    // 5. BN mean/istd + fused epilogue
    bnfinal_kernel<<<1, 3*CCH>>>();
    int writeSecond = (out_size >= 2*N1OUT) ? 1 : 0;
    finalize_kernel<<<dim3(9, 2*CCH, BATCH), 256>>>(x1, x2, y1, y2, y3, out, writeSecond);
}